// round 7
// baseline (speedup 1.0000x reference)
#include <cuda_runtime.h>
#include <cuda_bf16.h>
#include <cstdint>

#define BATCH   16
#define SEQ     512
#define DIM     128
#define HID     1024
#define NLAYER  6
#define NHEAD   16
#define HEADDIM 64
#define AHID    2730
#define APAD    2736
#define FPAD    5472              // row pitch for fused ff13 fp32 buffer
#define NTOK    8192
#define RSCALE  0.4082482904638630f
#define RMSEPS  1e-6f

#define SPITCH  40                // bf16 elems per smem row (80B, conflict-free)
#define NSTAGE  3

// ---------------------------------------------------------------------------
// Device scratch (allocation-free)
// ---------------------------------------------------------------------------
__device__ __nv_bfloat16 g_winh[131072],       g_winl[131072];
__device__ __nv_bfloat16 g_wqkvh[6*3145728],   g_wqkvl[6*3145728];   // [3072][1024]
__device__ __nv_bfloat16 g_woh [6*1048576],    g_wol [6*1048576];
__device__ __nv_bfloat16 g_w13h[6*5591040],    g_w13l[6*5591040];    // [5460][1024]
__device__ __nv_bfloat16 g_w2h [6*1024*APAD],  g_w2l [6*1024*APAD];  // [1024][APAD]
__device__ __nv_bfloat16 g_outwh[131072],      g_outwl[131072];
__device__ __nv_bfloat16 g_xh [1048576],       g_xl [1048576];
__device__ __nv_bfloat16 g_gh [8388608],       g_gl [8388608];
__device__ __nv_bfloat16 g_qh [8388608],       g_ql [8388608];
__device__ __nv_bfloat16 g_kh [8388608],       g_kl [8388608];
__device__ __nv_bfloat16 g_vth[8388608],       g_vtl[8388608];       // [HID][NTOK]
__device__ __nv_bfloat16 g_oh [8388608],       g_ol [8388608];
__device__ __nv_bfloat16 g_ph [67108864],      g_pl [67108864];
__device__ __nv_bfloat16 g_ffh[(size_t)NTOK*APAD], g_ffl[(size_t)NTOK*APAD];
__device__ float g_h   [8388608];
__device__ float g_qkvf[(size_t)NTOK*3072];
__device__ float g_sc  [67108864];
__device__ float g_ff13[(size_t)NTOK*FPAD];
__device__ float g_bqkv[6*3072];
__device__ float g_b13 [6*5460];
__device__ float g_cos [SEQ*32], g_sin[SEQ*32];

// ---------------------------------------------------------------------------
// PTX helpers
// ---------------------------------------------------------------------------
__device__ __forceinline__ void cp_async16(uint32_t dst, const void* src, int srcbytes) {
    asm volatile("cp.async.cg.shared.global [%0], [%1], 16, %2;\n"
                 :: "r"(dst), "l"(src), "r"(srcbytes));
}
#define CP_COMMIT() asm volatile("cp.async.commit_group;\n" ::)
#define CP_WAIT(n)  asm volatile("cp.async.wait_group %0;\n" :: "n"(n))

#define LDSM4(R0,R1,R2,R3,addr)                                               \
  asm volatile("ldmatrix.sync.aligned.m8n8.x4.shared.b16 {%0,%1,%2,%3}, [%4];"\
               : "=r"(R0),"=r"(R1),"=r"(R2),"=r"(R3) : "r"(addr))

#define MMA16816(d, A0,A1,A2,A3, B0,B1)                                       \
  asm volatile("mma.sync.aligned.m16n8k16.row.col.f32.bf16.bf16.f32 "         \
               "{%0,%1,%2,%3}, {%4,%5,%6,%7}, {%8,%9}, {%0,%1,%2,%3};"        \
               : "+f"(d[0]), "+f"(d[1]), "+f"(d[2]), "+f"(d[3])               \
               : "r"(A0), "r"(A1), "r"(A2), "r"(A3), "r"(B0), "r"(B1))

// ---------------------------------------------------------------------------
// Pipelined bf16 split GEMM (template over CTA tile width / warp grid).
// A: [M][K] hi/lo planes (lda). B: [N][K] hi/lo planes (ldb).
// C = alpha*(A@B^T + bias) (+C if accum). outmode 0: fp32; 1: bf16 hi/lo planes.
// Inner loop is TERM-MAJOR: all accumulators swept per split-term, so each
// accumulator's RAW reuse distance is 16-32 independent MMAs (no HMMA chains).
// ---------------------------------------------------------------------------
template<int NT, int WR, int WC>
__global__ void __launch_bounds__(256, 1)
gemm_mma_kernel(const __nv_bfloat16* __restrict__ Ah, const __nv_bfloat16* __restrict__ Al,
                const __nv_bfloat16* __restrict__ Bh, const __nv_bfloat16* __restrict__ Bl,
                float* __restrict__ C, __nv_bfloat16* __restrict__ Ch, __nv_bfloat16* __restrict__ Cl,
                const float* __restrict__ bias,
                int M, int N, int K, int lda, int ldb, int ldc,
                float alpha, int accum, int outmode, int bdiv,
                long long sA1, long long sA2, long long sB1, long long sB2,
                long long sC1, long long sC2)
{
    constexpr int WTM = 128 / WR;          // warp tile M
    constexpr int WTN = NT / WC;           // warp tile N
    constexpr int MT  = WTM / 16;
    constexpr int NTT = WTN / 8;
    constexpr int NH  = NTT / 4;           // B-fragment half-groups
    constexpr int APLANE = 128 * SPITCH;   // elems
    constexpr int BPLANE = NT * SPITCH;
    constexpr int STAGE_E = 2*APLANE + 2*BPLANE;

    extern __shared__ __nv_bfloat16 smem[];
    uint32_t sbase = (uint32_t)__cvta_generic_to_shared(smem);

    const int tid = threadIdx.x, lane = tid & 31, warp = tid >> 5;
    const int wm = warp / WC, wn = warp % WC;

    const int z = blockIdx.z, zq = z / bdiv, zr = z - zq * bdiv;
    const __nv_bfloat16* Abh = Ah + zq*sA1 + (long long)zr*sA2;
    const __nv_bfloat16* Abl = Al + zq*sA1 + (long long)zr*sA2;
    const __nv_bfloat16* Bbh = Bh + zq*sB1 + (long long)zr*sB2;
    const __nv_bfloat16* Bbl = Bl + zq*sB1 + (long long)zr*sB2;
    const long long coff = zq*sC1 + (long long)zr*sC2;

    const int m0 = blockIdx.y * 128, n0 = blockIdx.x * NT;
    const int T = (K + 31) >> 5;

    auto load_stage = [&](int stg, int k0) {
        uint32_t st = sbase + (uint32_t)stg * (STAGE_E * 2);
        #pragma unroll
        for (int i = 0; i < 2; i++) {               // A: 128 rows x 4 chunks
            int idx = tid + i*256;
            int r = idx >> 2, ch = idx & 3;
            int k = k0 + ch*8;
            int s = (K - k) * 2; s = s < 0 ? 0 : (s > 16 ? 16 : s);
            long long aoff = (long long)(m0 + r) * lda + (s ? k : 0);
            uint32_t d = st + (uint32_t)(r*SPITCH + ch*8)*2;
            cp_async16(d,            Abh + aoff, s);
            cp_async16(d + APLANE*2, Abl + aoff, s);
        }
        #pragma unroll
        for (int i = 0; i < NT/64; i++) {           // B: NT rows x 4 chunks
            int idx = tid + i*256;
            int r = idx >> 2, ch = idx & 3;
            int n = n0 + r;
            int k = k0 + ch*8;
            int s = (K - k) * 2; s = s < 0 ? 0 : (s > 16 ? 16 : s);
            if (n >= N) s = 0;
            long long boff = (long long)(n < N ? n : 0) * ldb + (s ? k : 0);
            uint32_t d = st + (uint32_t)(2*APLANE + r*SPITCH + ch*8)*2;
            cp_async16(d,            Bbh + boff, s);
            cp_async16(d + BPLANE*2, Bbl + boff, s);
        }
    };

    // prologue
    load_stage(0, 0);
    CP_COMMIT();
    if (T > 1) { load_stage(1, 32); CP_COMMIT(); }

    float acc[MT][NTT][4];
    #pragma unroll
    for (int i = 0; i < MT; i++)
        #pragma unroll
        for (int j = 0; j < NTT; j++)
            #pragma unroll
            for (int e = 0; e < 4; e++) acc[i][j][e] = 0.f;

    for (int kt = 0; kt < T; kt++) {
        if (kt + 1 < T) { CP_WAIT(1); } else { CP_WAIT(0); }
        __syncthreads();
        if (kt + 2 < T) { load_stage((kt + 2) % NSTAGE, (kt + 2) * 32); CP_COMMIT(); }

        uint32_t st = sbase + (uint32_t)((kt % NSTAGE) * (STAGE_E * 2));
        #pragma unroll
        for (int ks = 0; ks < 2; ks++) {
            const int c0 = ks*16 + ((lane >> 4) << 3);
            const int rr = lane & 15;
            uint32_t ah[MT][4], al[MT][4];
            #pragma unroll
            for (int mt = 0; mt < MT; mt++) {
                uint32_t ad = st + (uint32_t)(((wm*WTM + mt*16 + rr)*SPITCH + c0)*2);
                LDSM4(ah[mt][0], ah[mt][1], ah[mt][2], ah[mt][3], ad);
                LDSM4(al[mt][0], al[mt][1], al[mt][2], al[mt][3], ad + APLANE*2);
            }
            #pragma unroll
            for (int half = 0; half < NH; half++) {
                uint32_t bh[4][2], bl[4][2];
                #pragma unroll
                for (int p = 0; p < 2; p++) {
                    uint32_t bd = st + (uint32_t)((2*APLANE +
                                  (wn*WTN + half*32 + p*16 + rr)*SPITCH + c0)*2);
                    uint32_t r0, r1, r2, r3;
                    LDSM4(r0, r1, r2, r3, bd);
                    bh[2*p][0] = r0; bh[2*p+1][0] = r1; bh[2*p][1] = r2; bh[2*p+1][1] = r3;
                    LDSM4(r0, r1, r2, r3, bd + BPLANE*2);
                    bl[2*p][0] = r0; bl[2*p+1][0] = r1; bl[2*p][1] = r2; bl[2*p+1][1] = r3;
                }
                // term-major: sweep all accs per term (per-acc order hh,hl,lh preserved)
                #pragma unroll
                for (int mt = 0; mt < MT; mt++)
                    #pragma unroll
                    for (int j = 0; j < 4; j++)
                        MMA16816(acc[mt][half*4+j], ah[mt][0],ah[mt][1],ah[mt][2],ah[mt][3], bh[j][0],bh[j][1]);
                #pragma unroll
                for (int mt = 0; mt < MT; mt++)
                    #pragma unroll
                    for (int j = 0; j < 4; j++)
                        MMA16816(acc[mt][half*4+j], ah[mt][0],ah[mt][1],ah[mt][2],ah[mt][3], bl[j][0],bl[j][1]);
                #pragma unroll
                for (int mt = 0; mt < MT; mt++)
                    #pragma unroll
                    for (int j = 0; j < 4; j++)
                        MMA16816(acc[mt][half*4+j], al[mt][0],al[mt][1],al[mt][2],al[mt][3], bh[j][0],bh[j][1]);
            }
        }
    }

    // ---- epilogue ----
    const int g = lane >> 2, t4 = lane & 3;
    #pragma unroll
    for (int mt = 0; mt < MT; mt++)
        #pragma unroll
        for (int nt = 0; nt < NTT; nt++) {
            int r = m0 + wm*WTM + mt*16 + g;
            int c = n0 + wn*WTN + nt*8 + 2*t4;
            if (c < N) {
                float bv0 = 0.f, bv1 = 0.f;
                if (bias) { bv0 = bias[c]; bv1 = bias[c+1]; }
                #pragma unroll
                for (int hh = 0; hh < 2; hh++) {
                    int rr = r + hh*8;
                    float v0 = (acc[mt][nt][hh*2+0] + bv0) * alpha;
                    float v1 = (acc[mt][nt][hh*2+1] + bv1) * alpha;
                    long long off = coff + (long long)rr * ldc + c;
                    if (outmode == 0) {
                        float2 o;
                        if (accum) { float2 p = *(const float2*)(C + off); o.x = p.x + v0; o.y = p.y + v1; }
                        else       { o.x = v0; o.y = v1; }
                        *(float2*)(C + off) = o;
                    } else {
                        __nv_bfloat16 h0 = __float2bfloat16(v0);
                        __nv_bfloat16 h1 = __float2bfloat16(v1);
                        __nv_bfloat16 l0 = __float2bfloat16(v0 - __bfloat162float(h0));
                        __nv_bfloat16 l1 = __float2bfloat16(v1 - __bfloat162float(h1));
                        uint32_t ph = ((uint32_t)__bfloat16_as_ushort(h1) << 16) | __bfloat16_as_ushort(h0);
                        uint32_t pl = ((uint32_t)__bfloat16_as_ushort(l1) << 16) | __bfloat16_as_ushort(l0);
                        *(uint32_t*)(Ch + off) = ph;
                        *(uint32_t*)(Cl + off) = pl;
                    }
                }
            }
        }
}

// ---------------------------------------------------------------------------
// Producers / converters
// ---------------------------------------------------------------------------
__global__ void split_kernel(const float* __restrict__ src,
                             __nv_bfloat16* __restrict__ dh,
                             __nv_bfloat16* __restrict__ dl, long long n)
{
    long long i = (long long)blockIdx.x * blockDim.x + threadIdx.x;
    if (i >= n) return;
    float v = src[i];
    __nv_bfloat16 hi = __float2bfloat16(v);
    dh[i] = hi;
    dl[i] = __float2bfloat16(v - __bfloat162float(hi));
}

// transpose fp32 [R][srcPitch] (first C cols valid) -> bf16 planes [C][dstPitch]
__global__ void transpose_split_kernel(const float* __restrict__ src,
                                       __nv_bfloat16* __restrict__ dh,
                                       __nv_bfloat16* __restrict__ dl,
                                       int R, int C, int srcPitch, int dstPitch,
                                       long long srcZ, long long dstZ)
{
    __shared__ float t[32][33];
    long long so = (long long)blockIdx.z * srcZ;
    long long dofs = (long long)blockIdx.z * dstZ;
    int c0 = blockIdx.x*32, r0 = blockIdx.y*32;
    #pragma unroll
    for (int i = threadIdx.y; i < 32; i += 8) {
        int r = r0 + i, c = c0 + threadIdx.x;
        t[i][threadIdx.x] = (r < R && c < C) ? src[so + (long long)r*srcPitch + c] : 0.f;
    }
    __syncthreads();
    #pragma unroll
    for (int i = threadIdx.y; i < 32; i += 8) {
        int c = c0 + i, r = r0 + threadIdx.x;
        if (c < C && r < R) {
            float v = t[threadIdx.x][i];
            __nv_bfloat16 hi = __float2bfloat16(v);
            long long o = dofs + (long long)c*dstPitch + r;
            dh[o] = hi;
            dl[o] = __float2bfloat16(v - __bfloat162float(hi));
        }
    }
}

__global__ void rmsnorm_kernel(const float* __restrict__ x, const float* __restrict__ w,
                               __nv_bfloat16* __restrict__ oh, __nv_bfloat16* __restrict__ ol)
{
    long long row = blockIdx.x;
    const float* xr = x + row * HID;
    float s = 0.f;
    #pragma unroll
    for (int c = threadIdx.x; c < HID; c += 256) { float v = xr[c]; s += v * v; }
    #pragma unroll
    for (int o = 16; o; o >>= 1) s += __shfl_xor_sync(0xffffffffu, s, o);
    __shared__ float red[8];
    int warp = threadIdx.x >> 5, lane = threadIdx.x & 31;
    if (lane == 0) red[warp] = s;
    __syncthreads();
    float tot = red[0]+red[1]+red[2]+red[3]+red[4]+red[5]+red[6]+red[7];
    float inv = rsqrtf(tot * (1.0f / HID) + RMSEPS);
    #pragma unroll
    for (int c = threadIdx.x; c < HID; c += 256) {
        float v = xr[c] * inv * w[c];
        __nv_bfloat16 hi = __float2bfloat16(v);
        oh[row*HID + c] = hi;
        ol[row*HID + c] = __float2bfloat16(v - __bfloat162float(hi));
    }
}

__global__ void rope_cache_kernel()
{
    int i = blockIdx.x * blockDim.x + threadIdx.x;
    if (i >= SEQ * 32) return;
    int s = i >> 5, j = i & 31;
    float invf = expf(-(float)j * (1.0f / 32.0f) * logf(10000.0f));
    float a = (float)s * invf;
    g_cos[i] = cosf(a);
    g_sin[i] = sinf(a);
}

// reads fused qkv buffer [NTOK][3072]; writes roped q,k into hi/lo planes [NTOK][HID]
__global__ void rope_apply_kernel(const float* __restrict__ qkv)
{
    int i = blockIdx.x * blockDim.x + threadIdx.x;
    if (i >= NTOK * NHEAD * 32) return;
    int m = i >> 9, rem = i & 511;
    int h = rem >> 5, j = rem & 31;
    int s = m & (SEQ - 1);
    float c  = g_cos[s*32 + j];
    float sn = g_sin[s*32 + j];
    long long src = (long long)m * 3072 + h * HEADDIM + j;
    long long dst = (long long)m * HID  + h * HEADDIM + j;
    {
        float a = qkv[src], b = qkv[src + 32];
        float v0 = a * c - b * sn, v1 = b * c + a * sn;
        __nv_bfloat16 h0 = __float2bfloat16(v0), h1 = __float2bfloat16(v1);
        g_qh[dst]      = h0; g_ql[dst]      = __float2bfloat16(v0 - __bfloat162float(h0));
        g_qh[dst + 32] = h1; g_ql[dst + 32] = __float2bfloat16(v1 - __bfloat162float(h1));
    }
    {
        float a = qkv[src + HID], b = qkv[src + HID + 32];
        float v0 = a * c - b * sn, v1 = b * c + a * sn;
        __nv_bfloat16 h0 = __float2bfloat16(v0), h1 = __float2bfloat16(v1);
        g_kh[dst]      = h0; g_kl[dst]      = __float2bfloat16(v0 - __bfloat162float(h0));
        g_kh[dst + 32] = h1; g_kl[dst + 32] = __float2bfloat16(v1 - __bfloat162float(h1));
    }
}

__global__ void softmax_kernel(const float* __restrict__ sc,
                               __nv_bfloat16* __restrict__ ph, __nv_bfloat16* __restrict__ pl)
{
    long long row = (long long)blockIdx.x * 8 + (threadIdx.x >> 5);
    int lane = threadIdx.x & 31;
    const float* p = sc + row * SEQ;
    float e[16];
    float mx = -3.4e38f;
    #pragma unroll
    for (int i = 0; i < 16; i++) { e[i] = p[lane + i*32]; mx = fmaxf(mx, e[i]); }
    #pragma unroll
    for (int o = 16; o; o >>= 1) mx = fmaxf(mx, __shfl_xor_sync(0xffffffffu, mx, o));
    float sum = 0.f;
    #pragma unroll
    for (int i = 0; i < 16; i++) { e[i] = __expf(e[i] - mx); sum += e[i]; }
    #pragma unroll
    for (int o = 16; o; o >>= 1) sum += __shfl_xor_sync(0xffffffffu, sum, o);
    float r = 1.0f / sum;
    #pragma unroll
    for (int i = 0; i < 16; i++) {
        float v = e[i] * r;
        __nv_bfloat16 hi = __float2bfloat16(v);
        ph[row*SEQ + lane + i*32] = hi;
        pl[row*SEQ + lane + i*32] = __float2bfloat16(v - __bfloat162float(hi));
    }
}

// reads fused ff13 [NTOK][FPAD] (w1 out at cols [0,AHID), w3 out at [AHID,2*AHID))
__global__ void swiglu_kernel(const float* __restrict__ ff,
                              __nv_bfloat16* __restrict__ oh, __nv_bfloat16* __restrict__ ol)
{
    long long i = (long long)blockIdx.x * blockDim.x + threadIdx.x;
    if (i >= (long long)NTOK * AHID) return;
    long long r = i / AHID;
    int c = (int)(i - r * AHID);
    float a = ff[r*FPAD + c], b = ff[r*FPAD + AHID + c];
    float v = a / (1.0f + __expf(-a)) * b;
    __nv_bfloat16 hi = __float2bfloat16(v);
    long long o = r * APAD + c;
    oh[o] = hi;
    ol[o] = __float2bfloat16(v - __bfloat162float(hi));
}

// concat per-layer biases: dst[l][0:n1)=b1[l], [n1:n1+n2)=b2[l], [..+n3)=b3[l]
__global__ void concat_bias_kernel(const float* __restrict__ b1, const float* __restrict__ b2,
                                   const float* __restrict__ b3, float* __restrict__ dst,
                                   int n1, int n2, int n3)
{
    int tot = n1 + n2 + n3;
    int i = blockIdx.x * blockDim.x + threadIdx.x;
    if (i >= NLAYER * tot) return;
    int l = i / tot, r = i - l * tot;
    float v;
    if (r < n1)           v = b1[l*n1 + r];
    else if (r < n1 + n2) v = b2[l*n2 + (r - n1)];
    else                  v = b3[l*n3 + (r - n1 - n2)];
    dst[i] = v;
}

// ---------------------------------------------------------------------------
// Host plumbing
// ---------------------------------------------------------------------------
static inline size_t stage_bytes(int NT) { return (size_t)(2*128*SPITCH + 2*NT*SPITCH) * 2; }

static void gemm(const __nv_bfloat16* Ahp, const __nv_bfloat16* Alp,
                 const __nv_bfloat16* Bhp, const __nv_bfloat16* Blp,
                 float* C, __nv_bfloat16* Ch, __nv_bfloat16* Cl,
                 const float* bias, int M, int N, int K, int lda, int ldb, int ldc,
                 float alpha, int accum, int outmode, int NT,
                 int batches = 1, int bdiv = 1,
                 long long sA1 = 0, long long sA2 = 0,
                 long long sB1 = 0, long long sB2 = 0,
                 long long sC1 = 0, long long sC2 = 0)
{
    dim3 grid((N + NT - 1) / NT, M / 128, batches);
    size_t sm = NSTAGE * stage_bytes(NT);
    if (NT == 256)
        gemm_mma_kernel<256,2,4><<<grid, 256, sm>>>(Ahp, Alp, Bhp, Blp, C, Ch, Cl, bias,
            M, N, K, lda, ldb, ldc, alpha, accum, outmode, bdiv, sA1, sA2, sB1, sB2, sC1, sC2);
    else if (NT == 128)
        gemm_mma_kernel<128,4,2><<<grid, 256, sm>>>(Ahp, Alp, Bhp, Blp, C, Ch, Cl, bias,
            M, N, K, lda, ldb, ldc, alpha, accum, outmode, bdiv, sA1, sA2, sB1, sB2, sC1, sC2);
    else
        gemm_mma_kernel<64,4,2><<<grid, 256, sm>>>(Ahp, Alp, Bhp, Blp, C, Ch, Cl, bias,
            M, N, K, lda, ldb, ldc, alpha, accum, outmode, bdiv, sA1, sA2, sB1, sB2, sC1, sC2);
}

#define SYM(p, s) cudaGetSymbolAddress((void**)&p, s)

extern "C" void kernel_launch(void* const* d_in, const int* in_sizes, int n_in,
                              void* d_out, int out_size)
{
    const float* x       = (const float*)d_in[0];
    const float* in_w    = (const float*)d_in[1];
    const float* in_b    = (const float*)d_in[2];
    const float* norm1_w = (const float*)d_in[3];
    const float* norm2_w = (const float*)d_in[4];
    const float* wq      = (const float*)d_in[5];
    const float* bq      = (const float*)d_in[6];
    const float* wk      = (const float*)d_in[7];
    const float* bk      = (const float*)d_in[8];
    const float* wv      = (const float*)d_in[9];
    const float* bv      = (const float*)d_in[10];
    const float* wo      = (const float*)d_in[11];
    const float* bo      = (const float*)d_in[12];
    const float* w1      = (const float*)d_in[13];
    const float* b1      = (const float*)d_in[14];
    const float* w3      = (const float*)d_in[15];
    const float* b3      = (const float*)d_in[16];
    const float* w2      = (const float*)d_in[17];
    const float* b2      = (const float*)d_in[18];
    const float* onorm_w = (const float*)d_in[19];
    const float* out_w   = (const float*)d_in[20];
    const float* out_b   = (const float*)d_in[21];
    float* out = (float*)d_out;

    cudaFuncSetAttribute(gemm_mma_kernel<256,2,4>,
        cudaFuncAttributeMaxDynamicSharedMemorySize, (int)(NSTAGE * stage_bytes(256)));
    cudaFuncSetAttribute(gemm_mma_kernel<128,4,2>,
        cudaFuncAttributeMaxDynamicSharedMemorySize, (int)(NSTAGE * stage_bytes(128)));
    cudaFuncSetAttribute(gemm_mma_kernel<64,4,2>,
        cudaFuncAttributeMaxDynamicSharedMemorySize, (int)(NSTAGE * stage_bytes(64)));

    __nv_bfloat16 *winh,*winl,*wqkvh,*wqkvl,*woh,*wol,*w13h,*w13l,*w2h,*w2l,*outwh,*outwl;
    __nv_bfloat16 *xh,*xl,*gh,*gl,*qh,*ql,*kh,*kl,*vth,*vtl,*oh,*ol,*ph,*pl,*ffh,*ffl;
    float *h,*qkvf,*sc,*ff13,*bqkv,*b13;
    SYM(winh,g_winh); SYM(winl,g_winl);
    SYM(wqkvh,g_wqkvh); SYM(wqkvl,g_wqkvl);
    SYM(woh,g_woh); SYM(wol,g_wol);
    SYM(w13h,g_w13h); SYM(w13l,g_w13l);
    SYM(w2h,g_w2h); SYM(w2l,g_w2l);
    SYM(outwh,g_outwh); SYM(outwl,g_outwl);
    SYM(xh,g_xh); SYM(xl,g_xl); SYM(gh,g_gh); SYM(gl,g_gl);
    SYM(qh,g_qh); SYM(ql,g_ql); SYM(kh,g_kh); SYM(kl,g_kl);
    SYM(vth,g_vth); SYM(vtl,g_vtl); SYM(oh,g_oh); SYM(ol,g_ol);
    SYM(ph,g_ph); SYM(pl,g_pl); SYM(ffh,g_ffh); SYM(ffl,g_ffl);
    SYM(h,g_h); SYM(qkvf,g_qkvf); SYM(sc,g_sc); SYM(ff13,g_ff13);
    SYM(bqkv,g_bqkv); SYM(b13,g_b13);

    const long long HH  = (long long)HID*HID;
    const long long HA  = (long long)HID*AHID;
    const long long QKV = (long long)3072*HID;   // per-layer fused qkv weight plane
    const long long F13 = (long long)5460*HID;   // per-layer fused ff13 weight plane

    // ---- one-time converters ----
    rope_cache_kernel<<<(SEQ*32 + 255)/256, 256>>>();
    split_kernel<<<(1048576 + 255)/256, 256>>>(x, xh, xl, 1048576);
    concat_bias_kernel<<<(NLAYER*3072 + 255)/256, 256>>>(bq, bk, bv, bqkv, HID, HID, HID);
    concat_bias_kernel<<<(NLAYER*5460 + 255)/256, 256>>>(b1, b3, b1, b13, AHID, AHID, 0);
    {
        dim3 b(32, 8);
        transpose_split_kernel<<<dim3(32, 4, 1),  b>>>(in_w,  winh, winl, DIM,  HID, HID, DIM,  0, 0);
        // fused qkv weight: rows [0,1024)=wq^T, [1024,2048)=wk^T, [2048,3072)=wv^T
        transpose_split_kernel<<<dim3(32, 32, 6), b>>>(wq, wqkvh,            wqkvl,            HID, HID, HID, HID, HH, QKV);
        transpose_split_kernel<<<dim3(32, 32, 6), b>>>(wk, wqkvh + 1024*HID, wqkvl + 1024*HID, HID, HID, HID, HID, HH, QKV);
        transpose_split_kernel<<<dim3(32, 32, 6), b>>>(wv, wqkvh + 2048*HID, wqkvl + 2048*HID, HID, HID, HID, HID, HH, QKV);
        transpose_split_kernel<<<dim3(32, 32, 6), b>>>(wo, woh, wol, HID, HID, HID, HID, HH, HH);
        // fused ff13 weight: rows [0,2730)=w1^T, [2730,5460)=w3^T
        transpose_split_kernel<<<dim3(86, 32, 6), b>>>(w1, w13h,             w13l,             HID, AHID, AHID, HID, HA, F13);
        transpose_split_kernel<<<dim3(86, 32, 6), b>>>(w3, w13h + (long long)AHID*HID, w13l + (long long)AHID*HID, HID, AHID, AHID, HID, HA, F13);
        transpose_split_kernel<<<dim3(32, 86, 6), b>>>(w2, w2h, w2l, AHID, HID, HID, APAD, HA, (long long)HID*APAD);
        transpose_split_kernel<<<dim3(4, 32, 1),  b>>>(out_w, outwh, outwl, HID, DIM, DIM, HID, 0, 0);
    }

    // h = x @ in_w + in_b
    gemm(xh, xl, winh, winl, h, nullptr, nullptr, in_b,
         NTOK, HID, DIM, DIM, DIM, HID, 1.0f, 0, 0, 256);

    for (int l = 0; l < NLAYER; l++) {
        rmsnorm_kernel<<<NTOK, 256>>>(h, norm1_w + (long long)l*HID, gh, gl);

        // fused qkv: [NTOK][3072]
        gemm(gh, gl, wqkvh + l*QKV, wqkvl + l*QKV, qkvf, nullptr, nullptr, bqkv + (long long)l*3072,
             NTOK, 3072, HID, HID, HID, 3072, 1.0f, 0, 0, 256);

        rope_apply_kernel<<<(NTOK*NHEAD*32 + 255)/256, 256>>>(qkvf);
        transpose_split_kernel<<<dim3(32, 256, 1), dim3(32,8)>>>(qkvf + 2048, vth, vtl,
                                                                 NTOK, HID, 3072, NTOK, 0, 0);

        // scores = 0.125 * Q K^T  (z = b*NHEAD + head)
        gemm(qh, ql, kh, kl, sc, nullptr, nullptr, nullptr,
             SEQ, SEQ, HEADDIM, HID, HID, SEQ, 0.125f, 0, 0, 256,
             BATCH*NHEAD, NHEAD,
             (long long)SEQ*HID, HEADDIM,
             (long long)SEQ*HID, HEADDIM,
             (long long)NHEAD*SEQ*SEQ, (long long)SEQ*SEQ);

        softmax_kernel<<<BATCH*NHEAD*SEQ/8, 256>>>(sc, ph, pl);

        // o = P @ V  (bf16 hi/lo planes out)
        gemm(ph, pl, vth, vtl, nullptr, oh, ol, nullptr,
             SEQ, HEADDIM, SEQ, SEQ, NTOK, HID, 1.0f, 0, 1, 64,
             BATCH*NHEAD, NHEAD,
             (long long)NHEAD*SEQ*SEQ, (long long)SEQ*SEQ,
             (long long)SEQ, (long long)HEADDIM*NTOK,
             (long long)SEQ*HID, (long long)HEADDIM);

        // h += (o @ wo + bo) * RS
        gemm(oh, ol, woh + l*HH, wol + l*HH, h, nullptr, nullptr, bo + (long long)l*HID,
             NTOK, HID, HID, HID, HID, HID, RSCALE, 1, 0, 256);

        rmsnorm_kernel<<<NTOK, 256>>>(h, norm2_w + (long long)l*HID, gh, gl);

        // fused ff13: [NTOK][5460] (pitch FPAD)
        gemm(gh, gl, w13h + l*F13, w13l + l*F13, ff13, nullptr, nullptr, b13 + (long long)l*5460,
             NTOK, 5460, HID, HID, HID, FPAD, 1.0f, 0, 0, 256);

        {
            long long n = (long long)NTOK * AHID;
            swiglu_kernel<<<(unsigned)((n + 255) / 256), 256>>>(ff13, ffh, ffl);
        }

        // h += (ffg @ w2 + b2) * RS
        gemm(ffh, ffl, w2h + (long long)l*HID*APAD, w2l + (long long)l*HID*APAD, h,
             nullptr, nullptr, b2 + (long long)l*HID,
             NTOK, HID, AHID, APAD, APAD, HID, RSCALE, 1, 0, 256);
    }

    rmsnorm_kernel<<<NTOK, 256>>>(h, onorm_w, gh, gl);
    gemm(gh, gl, outwh, outwl, out, nullptr, nullptr, out_b,
         NTOK, DIM, HID, HID, HID, DIM, 1.0f, 0, 0, 128);
}

// round 8
// speedup vs baseline: 1.1230x; 1.1230x over previous
#include <cuda_runtime.h>
#include <cuda_bf16.h>
#include <cstdint>

#define BATCH   16
#define SEQ     512
#define DIM     128
#define HID     1024
#define NLAYER  6
#define NHEAD   16
#define HEADDIM 64
#define AHID    2730
#define APAD    2736
#define NTOK    8192
#define RSCALE  0.4082482904638630f
#define RMSEPS  1e-6f

#define SPITCH  40                // bf16 elems per smem row (80B, conflict-free)

// ---------------------------------------------------------------------------
// Device scratch (allocation-free)
// ---------------------------------------------------------------------------
__device__ __nv_bfloat16 g_winh[131072],       g_winl[131072];
__device__ __nv_bfloat16 g_wqkvh[6*3145728],   g_wqkvl[6*3145728];   // [3072][1024]
__device__ __nv_bfloat16 g_woh [6*1048576],    g_wol [6*1048576];
__device__ __nv_bfloat16 g_w13h[6*5591040],    g_w13l[6*5591040];    // [5460][1024] row-interleaved w1/w3
__device__ __nv_bfloat16 g_w2h [6*1024*APAD],  g_w2l [6*1024*APAD];  // [1024][APAD]
__device__ __nv_bfloat16 g_outwh[131072],      g_outwl[131072];
__device__ __nv_bfloat16 g_xh [1048576],       g_xl [1048576];
__device__ __nv_bfloat16 g_gh [8388608],       g_gl [8388608];
__device__ __nv_bfloat16 g_qh [8388608],       g_ql [8388608];
__device__ __nv_bfloat16 g_kh [8388608],       g_kl [8388608];
__device__ __nv_bfloat16 g_vth[8388608],       g_vtl[8388608];       // [HID][NTOK]
__device__ __nv_bfloat16 g_oh [8388608],       g_ol [8388608];
__device__ __nv_bfloat16 g_ph [67108864],      g_pl [67108864];
__device__ __nv_bfloat16 g_ffh[(size_t)NTOK*APAD], g_ffl[(size_t)NTOK*APAD];
__device__ float g_h   [8388608];
__device__ float g_qkvf[(size_t)NTOK*3072];
__device__ float g_sc  [67108864];
__device__ float g_bqkv[6*3072];
__device__ float g_b13i[6*5460];               // interleaved b1/b3
__device__ float g_cos [SEQ*32], g_sin[SEQ*32];

// ---------------------------------------------------------------------------
// PTX helpers
// ---------------------------------------------------------------------------
__device__ __forceinline__ void cp_async16(uint32_t dst, const void* src, int srcbytes) {
    asm volatile("cp.async.cg.shared.global [%0], [%1], 16, %2;\n"
                 :: "r"(dst), "l"(src), "r"(srcbytes));
}
#define CP_COMMIT() asm volatile("cp.async.commit_group;\n" ::)
#define CP_WAIT(n)  asm volatile("cp.async.wait_group %0;\n" :: "n"(n))

#define LDSM4(R0,R1,R2,R3,addr)                                               \
  asm volatile("ldmatrix.sync.aligned.m8n8.x4.shared.b16 {%0,%1,%2,%3}, [%4];"\
               : "=r"(R0),"=r"(R1),"=r"(R2),"=r"(R3) : "r"(addr))

#define MMA16816(d, A0,A1,A2,A3, B0,B1)                                       \
  asm volatile("mma.sync.aligned.m16n8k16.row.col.f32.bf16.bf16.f32 "         \
               "{%0,%1,%2,%3}, {%4,%5,%6,%7}, {%8,%9}, {%0,%1,%2,%3};"        \
               : "+f"(d[0]), "+f"(d[1]), "+f"(d[2]), "+f"(d[3])               \
               : "r"(A0), "r"(A1), "r"(A2), "r"(A3), "r"(B0), "r"(B1))

// ---------------------------------------------------------------------------
// Pipelined bf16 split GEMM, 2 CTAs/SM, double-buffered (NSTAGE=2).
// A: [M][K] hi/lo planes (lda). B: [N][K] hi/lo planes (ldb).
// outmode 0: fp32 C (+bias,*alpha,+=C); 1: bf16 hi/lo planes;
// outmode 2: SwiGLU pair-fused: even col=w1, odd col=w3 -> silu(a)*b at col c/2.
// ---------------------------------------------------------------------------
template<int NT, int WR, int WC>
__global__ void __launch_bounds__(256, 2)
gemm_mma_kernel(const __nv_bfloat16* __restrict__ Ah, const __nv_bfloat16* __restrict__ Al,
                const __nv_bfloat16* __restrict__ Bh, const __nv_bfloat16* __restrict__ Bl,
                float* __restrict__ C, __nv_bfloat16* __restrict__ Ch, __nv_bfloat16* __restrict__ Cl,
                const float* __restrict__ bias,
                int M, int N, int K, int lda, int ldb, int ldc,
                float alpha, int accum, int outmode, int bdiv,
                long long sA1, long long sA2, long long sB1, long long sB2,
                long long sC1, long long sC2)
{
    constexpr int WTM = 128 / WR;
    constexpr int WTN = NT / WC;
    constexpr int MT  = WTM / 16;
    constexpr int NTT = WTN / 8;
    constexpr int NH  = NTT / 4;
    constexpr int APLANE = 128 * SPITCH;
    constexpr int BPLANE = NT * SPITCH;
    constexpr int STAGE_E = 2*APLANE + 2*BPLANE;

    extern __shared__ __nv_bfloat16 smem[];
    uint32_t sbase = (uint32_t)__cvta_generic_to_shared(smem);

    const int tid = threadIdx.x, lane = tid & 31, warp = tid >> 5;
    const int wm = warp / WC, wn = warp % WC;

    const int z = blockIdx.z, zq = z / bdiv, zr = z - zq * bdiv;
    const __nv_bfloat16* Abh = Ah + zq*sA1 + (long long)zr*sA2;
    const __nv_bfloat16* Abl = Al + zq*sA1 + (long long)zr*sA2;
    const __nv_bfloat16* Bbh = Bh + zq*sB1 + (long long)zr*sB2;
    const __nv_bfloat16* Bbl = Bl + zq*sB1 + (long long)zr*sB2;
    const long long coff = zq*sC1 + (long long)zr*sC2;

    const int m0 = blockIdx.y * 128, n0 = blockIdx.x * NT;
    const int T = (K + 31) >> 5;

    auto load_stage = [&](int stg, int k0) {
        uint32_t st = sbase + (uint32_t)stg * (STAGE_E * 2);
        #pragma unroll
        for (int i = 0; i < 2; i++) {               // A: 128 rows x 4 chunks
            int idx = tid + i*256;
            int r = idx >> 2, ch = idx & 3;
            int k = k0 + ch*8;
            int s = (K - k) * 2; s = s < 0 ? 0 : (s > 16 ? 16 : s);
            long long aoff = (long long)(m0 + r) * lda + (s ? k : 0);
            uint32_t d = st + (uint32_t)(r*SPITCH + ch*8)*2;
            cp_async16(d,            Abh + aoff, s);
            cp_async16(d + APLANE*2, Abl + aoff, s);
        }
        #pragma unroll
        for (int i = 0; i < NT/64; i++) {           // B: NT rows x 4 chunks
            int idx = tid + i*256;
            int r = idx >> 2, ch = idx & 3;
            int n = n0 + r;
            int k = k0 + ch*8;
            int s = (K - k) * 2; s = s < 0 ? 0 : (s > 16 ? 16 : s);
            if (n >= N) s = 0;
            long long boff = (long long)(n < N ? n : 0) * ldb + (s ? k : 0);
            uint32_t d = st + (uint32_t)(2*APLANE + r*SPITCH + ch*8)*2;
            cp_async16(d,            Bbh + boff, s);
            cp_async16(d + BPLANE*2, Bbl + boff, s);
        }
    };

    // prologue
    load_stage(0, 0);
    CP_COMMIT();

    float acc[MT][NTT][4];
    #pragma unroll
    for (int i = 0; i < MT; i++)
        #pragma unroll
        for (int j = 0; j < NTT; j++)
            #pragma unroll
            for (int e = 0; e < 4; e++) acc[i][j][e] = 0.f;

    for (int kt = 0; kt < T; kt++) {
        CP_WAIT(0);
        __syncthreads();
        if (kt + 1 < T) { load_stage((kt + 1) & 1, (kt + 1) * 32); CP_COMMIT(); }

        uint32_t st = sbase + (uint32_t)((kt & 1) * (STAGE_E * 2));
        #pragma unroll
        for (int ks = 0; ks < 2; ks++) {
            const int c0 = ks*16 + ((lane >> 4) << 3);
            const int rr = lane & 15;
            uint32_t ah[MT][4], al[MT][4];
            #pragma unroll
            for (int mt = 0; mt < MT; mt++) {
                uint32_t ad = st + (uint32_t)(((wm*WTM + mt*16 + rr)*SPITCH + c0)*2);
                LDSM4(ah[mt][0], ah[mt][1], ah[mt][2], ah[mt][3], ad);
                LDSM4(al[mt][0], al[mt][1], al[mt][2], al[mt][3], ad + APLANE*2);
            }
            #pragma unroll
            for (int half = 0; half < NH; half++) {
                uint32_t bh[4][2], bl[4][2];
                #pragma unroll
                for (int p = 0; p < 2; p++) {
                    uint32_t bd = st + (uint32_t)((2*APLANE +
                                  (wn*WTN + half*32 + p*16 + rr)*SPITCH + c0)*2);
                    uint32_t r0, r1, r2, r3;
                    LDSM4(r0, r1, r2, r3, bd);
                    bh[2*p][0] = r0; bh[2*p+1][0] = r1; bh[2*p][1] = r2; bh[2*p+1][1] = r3;
                    LDSM4(r0, r1, r2, r3, bd + BPLANE*2);
                    bl[2*p][0] = r0; bl[2*p+1][0] = r1; bl[2*p][1] = r2; bl[2*p+1][1] = r3;
                }
                #pragma unroll
                for (int mt = 0; mt < MT; mt++)
                    #pragma unroll
                    for (int j = 0; j < 4; j++)
                        MMA16816(acc[mt][half*4+j], ah[mt][0],ah[mt][1],ah[mt][2],ah[mt][3], bh[j][0],bh[j][1]);
                #pragma unroll
                for (int mt = 0; mt < MT; mt++)
                    #pragma unroll
                    for (int j = 0; j < 4; j++)
                        MMA16816(acc[mt][half*4+j], ah[mt][0],ah[mt][1],ah[mt][2],ah[mt][3], bl[j][0],bl[j][1]);
                #pragma unroll
                for (int mt = 0; mt < MT; mt++)
                    #pragma unroll
                    for (int j = 0; j < 4; j++)
                        MMA16816(acc[mt][half*4+j], al[mt][0],al[mt][1],al[mt][2],al[mt][3], bh[j][0],bh[j][1]);
            }
        }
    }

    // ---- epilogue ----
    const int g = lane >> 2, t4 = lane & 3;
    #pragma unroll
    for (int mt = 0; mt < MT; mt++)
        #pragma unroll
        for (int nt = 0; nt < NTT; nt++) {
            int r = m0 + wm*WTM + mt*16 + g;
            int c = n0 + wn*WTN + nt*8 + 2*t4;
            if (c < N) {
                float bv0 = 0.f, bv1 = 0.f;
                if (bias) { bv0 = bias[c]; bv1 = bias[c+1]; }
                #pragma unroll
                for (int hh = 0; hh < 2; hh++) {
                    int rr = r + hh*8;
                    float v0 = acc[mt][nt][hh*2+0] + bv0;
                    float v1 = acc[mt][nt][hh*2+1] + bv1;
                    if (outmode == 0) {
                        v0 *= alpha; v1 *= alpha;
                        long long off = coff + (long long)rr * ldc + c;
                        float2 o;
                        if (accum) { float2 p = *(const float2*)(C + off); o.x = p.x + v0; o.y = p.y + v1; }
                        else       { o.x = v0; o.y = v1; }
                        *(float2*)(C + off) = o;
                    } else if (outmode == 1) {
                        v0 *= alpha; v1 *= alpha;
                        long long off = coff + (long long)rr * ldc + c;
                        __nv_bfloat16 h0 = __float2bfloat16(v0);
                        __nv_bfloat16 h1 = __float2bfloat16(v1);
                        __nv_bfloat16 l0 = __float2bfloat16(v0 - __bfloat162float(h0));
                        __nv_bfloat16 l1 = __float2bfloat16(v1 - __bfloat162float(h1));
                        uint32_t ph = ((uint32_t)__bfloat16_as_ushort(h1) << 16) | __bfloat16_as_ushort(h0);
                        uint32_t pl = ((uint32_t)__bfloat16_as_ushort(l1) << 16) | __bfloat16_as_ushort(l0);
                        *(uint32_t*)(Ch + off) = ph;
                        *(uint32_t*)(Cl + off) = pl;
                    } else {
                        // SwiGLU fused: v0 = w1-path (a), v1 = w3-path (b)
                        float v = v0 / (1.0f + __expf(-v0)) * v1;
                        long long off = coff + (long long)rr * ldc + (c >> 1);
                        __nv_bfloat16 hi = __float2bfloat16(v);
                        Ch[off] = hi;
                        Cl[off] = __float2bfloat16(v - __bfloat162float(hi));
                    }
                }
            }
        }
}

// ---------------------------------------------------------------------------
// Producers / converters
// ---------------------------------------------------------------------------
__global__ void split_kernel(const float* __restrict__ src,
                             __nv_bfloat16* __restrict__ dh,
                             __nv_bfloat16* __restrict__ dl, long long n)
{
    long long i = (long long)blockIdx.x * blockDim.x + threadIdx.x;
    if (i >= n) return;
    float v = src[i];
    __nv_bfloat16 hi = __float2bfloat16(v);
    dh[i] = hi;
    dl[i] = __float2bfloat16(v - __bfloat162float(hi));
}

// transpose fp32 [R][srcPitch] (first C cols valid) -> bf16 planes, dst row = c*rowMul+rowAdd
__global__ void transpose_split_kernel(const float* __restrict__ src,
                                       __nv_bfloat16* __restrict__ dh,
                                       __nv_bfloat16* __restrict__ dl,
                                       int R, int C, int srcPitch, int dstPitch,
                                       int rowMul, int rowAdd,
                                       long long srcZ, long long dstZ)
{
    __shared__ float t[32][33];
    long long so = (long long)blockIdx.z * srcZ;
    long long dofs = (long long)blockIdx.z * dstZ;
    int c0 = blockIdx.x*32, r0 = blockIdx.y*32;
    #pragma unroll
    for (int i = threadIdx.y; i < 32; i += 8) {
        int r = r0 + i, c = c0 + threadIdx.x;
        t[i][threadIdx.x] = (r < R && c < C) ? src[so + (long long)r*srcPitch + c] : 0.f;
    }
    __syncthreads();
    #pragma unroll
    for (int i = threadIdx.y; i < 32; i += 8) {
        int c = c0 + i, r = r0 + threadIdx.x;
        if (c < C && r < R) {
            float v = t[threadIdx.x][i];
            __nv_bfloat16 hi = __float2bfloat16(v);
            long long o = dofs + (long long)(c*rowMul + rowAdd)*dstPitch + r;
            dh[o] = hi;
            dl[o] = __float2bfloat16(v - __bfloat162float(hi));
        }
    }
}

__global__ void rmsnorm_kernel(const float* __restrict__ x, const float* __restrict__ w,
                               __nv_bfloat16* __restrict__ oh, __nv_bfloat16* __restrict__ ol)
{
    long long row = blockIdx.x;
    const float* xr = x + row * HID;
    float s = 0.f;
    #pragma unroll
    for (int c = threadIdx.x; c < HID; c += 256) { float v = xr[c]; s += v * v; }
    #pragma unroll
    for (int o = 16; o; o >>= 1) s += __shfl_xor_sync(0xffffffffu, s, o);
    __shared__ float red[8];
    int warp = threadIdx.x >> 5, lane = threadIdx.x & 31;
    if (lane == 0) red[warp] = s;
    __syncthreads();
    float tot = red[0]+red[1]+red[2]+red[3]+red[4]+red[5]+red[6]+red[7];
    float inv = rsqrtf(tot * (1.0f / HID) + RMSEPS);
    #pragma unroll
    for (int c = threadIdx.x; c < HID; c += 256) {
        float v = xr[c] * inv * w[c];
        __nv_bfloat16 hi = __float2bfloat16(v);
        oh[row*HID + c] = hi;
        ol[row*HID + c] = __float2bfloat16(v - __bfloat162float(hi));
    }
}

__global__ void rope_cache_kernel()
{
    int i = blockIdx.x * blockDim.x + threadIdx.x;
    if (i >= SEQ * 32) return;
    int s = i >> 5, j = i & 31;
    float invf = expf(-(float)j * (1.0f / 32.0f) * logf(10000.0f));
    float a = (float)s * invf;
    g_cos[i] = cosf(a);
    g_sin[i] = sinf(a);
}

__global__ void rope_apply_kernel(const float* __restrict__ qkv)
{
    int i = blockIdx.x * blockDim.x + threadIdx.x;
    if (i >= NTOK * NHEAD * 32) return;
    int m = i >> 9, rem = i & 511;
    int h = rem >> 5, j = rem & 31;
    int s = m & (SEQ - 1);
    float c  = g_cos[s*32 + j];
    float sn = g_sin[s*32 + j];
    long long src = (long long)m * 3072 + h * HEADDIM + j;
    long long dst = (long long)m * HID  + h * HEADDIM + j;
    {
        float a = qkv[src], b = qkv[src + 32];
        float v0 = a * c - b * sn, v1 = b * c + a * sn;
        __nv_bfloat16 h0 = __float2bfloat16(v0), h1 = __float2bfloat16(v1);
        g_qh[dst]      = h0; g_ql[dst]      = __float2bfloat16(v0 - __bfloat162float(h0));
        g_qh[dst + 32] = h1; g_ql[dst + 32] = __float2bfloat16(v1 - __bfloat162float(h1));
    }
    {
        float a = qkv[src + HID], b = qkv[src + HID + 32];
        float v0 = a * c - b * sn, v1 = b * c + a * sn;
        __nv_bfloat16 h0 = __float2bfloat16(v0), h1 = __float2bfloat16(v1);
        g_kh[dst]      = h0; g_kl[dst]      = __float2bfloat16(v0 - __bfloat162float(h0));
        g_kh[dst + 32] = h1; g_kl[dst + 32] = __float2bfloat16(v1 - __bfloat162float(h1));
    }
}

__global__ void softmax_kernel(const float* __restrict__ sc,
                               __nv_bfloat16* __restrict__ ph, __nv_bfloat16* __restrict__ pl)
{
    long long row = (long long)blockIdx.x * 8 + (threadIdx.x >> 5);
    int lane = threadIdx.x & 31;
    const float* p = sc + row * SEQ;
    float e[16];
    float mx = -3.4e38f;
    #pragma unroll
    for (int i = 0; i < 16; i++) { e[i] = p[lane + i*32]; mx = fmaxf(mx, e[i]); }
    #pragma unroll
    for (int o = 16; o; o >>= 1) mx = fmaxf(mx, __shfl_xor_sync(0xffffffffu, mx, o));
    float sum = 0.f;
    #pragma unroll
    for (int i = 0; i < 16; i++) { e[i] = __expf(e[i] - mx); sum += e[i]; }
    #pragma unroll
    for (int o = 16; o; o >>= 1) sum += __shfl_xor_sync(0xffffffffu, sum, o);
    float r = 1.0f / sum;
    #pragma unroll
    for (int i = 0; i < 16; i++) {
        float v = e[i] * r;
        __nv_bfloat16 hi = __float2bfloat16(v);
        ph[row*SEQ + lane + i*32] = hi;
        pl[row*SEQ + lane + i*32] = __float2bfloat16(v - __bfloat162float(hi));
    }
}

// interleave per-layer b1/b3: dst[l][2j]=b1[l][j], dst[l][2j+1]=b3[l][j]
__global__ void interleave_bias_kernel(const float* __restrict__ b1, const float* __restrict__ b3,
                                       float* __restrict__ dst)
{
    int i = blockIdx.x * blockDim.x + threadIdx.x;
    if (i >= NLAYER * AHID) return;
    int l = i / AHID, j = i - l * AHID;
    dst[(long long)l*5460 + 2*j]     = b1[(long long)l*AHID + j];
    dst[(long long)l*5460 + 2*j + 1] = b3[(long long)l*AHID + j];
}

// concat per-layer biases (for qkv)
__global__ void concat_bias_kernel(const float* __restrict__ b1, const float* __restrict__ b2,
                                   const float* __restrict__ b3, float* __restrict__ dst,
                                   int n1, int n2, int n3)
{
    int tot = n1 + n2 + n3;
    int i = blockIdx.x * blockDim.x + threadIdx.x;
    if (i >= NLAYER * tot) return;
    int l = i / tot, r = i - l * tot;
    float v;
    if (r < n1)           v = b1[l*n1 + r];
    else if (r < n1 + n2) v = b2[l*n2 + (r - n1)];
    else                  v = b3[l*n3 + (r - n1 - n2)];
    dst[i] = v;
}

// ---------------------------------------------------------------------------
// Host plumbing
// ---------------------------------------------------------------------------
static inline size_t stage_bytes(int NT) { return (size_t)(2*128*SPITCH + 2*NT*SPITCH) * 2; }

static void gemm(const __nv_bfloat16* Ahp, const __nv_bfloat16* Alp,
                 const __nv_bfloat16* Bhp, const __nv_bfloat16* Blp,
                 float* C, __nv_bfloat16* Ch, __nv_bfloat16* Cl,
                 const float* bias, int M, int N, int K, int lda, int ldb, int ldc,
                 float alpha, int accum, int outmode, int NT,
                 int batches = 1, int bdiv = 1,
                 long long sA1 = 0, long long sA2 = 0,
                 long long sB1 = 0, long long sB2 = 0,
                 long long sC1 = 0, long long sC2 = 0)
{
    dim3 grid((N + NT - 1) / NT, M / 128, batches);
    size_t sm = 2 * stage_bytes(NT);
    if (NT == 128)
        gemm_mma_kernel<128,4,2><<<grid, 256, sm>>>(Ahp, Alp, Bhp, Blp, C, Ch, Cl, bias,
            M, N, K, lda, ldb, ldc, alpha, accum, outmode, bdiv, sA1, sA2, sB1, sB2, sC1, sC2);
    else
        gemm_mma_kernel<64,4,2><<<grid, 256, sm>>>(Ahp, Alp, Bhp, Blp, C, Ch, Cl, bias,
            M, N, K, lda, ldb, ldc, alpha, accum, outmode, bdiv, sA1, sA2, sB1, sB2, sC1, sC2);
}

#define SYM(p, s) cudaGetSymbolAddress((void**)&p, s)

extern "C" void kernel_launch(void* const* d_in, const int* in_sizes, int n_in,
                              void* d_out, int out_size)
{
    const float* x       = (const float*)d_in[0];
    const float* in_w    = (const float*)d_in[1];
    const float* in_b    = (const float*)d_in[2];
    const float* norm1_w = (const float*)d_in[3];
    const float* norm2_w = (const float*)d_in[4];
    const float* wq      = (const float*)d_in[5];
    const float* bq      = (const float*)d_in[6];
    const float* wk      = (const float*)d_in[7];
    const float* bk      = (const float*)d_in[8];
    const float* wv      = (const float*)d_in[9];
    const float* bv      = (const float*)d_in[10];
    const float* wo      = (const float*)d_in[11];
    const float* bo      = (const float*)d_in[12];
    const float* w1      = (const float*)d_in[13];
    const float* b1      = (const float*)d_in[14];
    const float* w3      = (const float*)d_in[15];
    const float* b3      = (const float*)d_in[16];
    const float* w2      = (const float*)d_in[17];
    const float* b2      = (const float*)d_in[18];
    const float* onorm_w = (const float*)d_in[19];
    const float* out_w   = (const float*)d_in[20];
    const float* out_b   = (const float*)d_in[21];
    float* out = (float*)d_out;

    cudaFuncSetAttribute(gemm_mma_kernel<128,4,2>,
        cudaFuncAttributeMaxDynamicSharedMemorySize, (int)(2 * stage_bytes(128)));
    cudaFuncSetAttribute(gemm_mma_kernel<64,4,2>,
        cudaFuncAttributeMaxDynamicSharedMemorySize, (int)(2 * stage_bytes(64)));

    __nv_bfloat16 *winh,*winl,*wqkvh,*wqkvl,*woh,*wol,*w13h,*w13l,*w2h,*w2l,*outwh,*outwl;
    __nv_bfloat16 *xh,*xl,*gh,*gl,*qh,*ql,*kh,*kl,*vth,*vtl,*oh,*ol,*ph,*pl,*ffh,*ffl;
    float *h,*qkvf,*sc,*bqkv,*b13i;
    SYM(winh,g_winh); SYM(winl,g_winl);
    SYM(wqkvh,g_wqkvh); SYM(wqkvl,g_wqkvl);
    SYM(woh,g_woh); SYM(wol,g_wol);
    SYM(w13h,g_w13h); SYM(w13l,g_w13l);
    SYM(w2h,g_w2h); SYM(w2l,g_w2l);
    SYM(outwh,g_outwh); SYM(outwl,g_outwl);
    SYM(xh,g_xh); SYM(xl,g_xl); SYM(gh,g_gh); SYM(gl,g_gl);
    SYM(qh,g_qh); SYM(ql,g_ql); SYM(kh,g_kh); SYM(kl,g_kl);
    SYM(vth,g_vth); SYM(vtl,g_vtl); SYM(oh,g_oh); SYM(ol,g_ol);
    SYM(ph,g_ph); SYM(pl,g_pl); SYM(ffh,g_ffh); SYM(ffl,g_ffl);
    SYM(h,g_h); SYM(qkvf,g_qkvf); SYM(sc,g_sc);
    SYM(bqkv,g_bqkv); SYM(b13i,g_b13i);

    const long long HH  = (long long)HID*HID;
    const long long HA  = (long long)HID*AHID;
    const long long QKV = (long long)3072*HID;
    const long long F13 = (long long)5460*HID;

    // ---- one-time converters ----
    rope_cache_kernel<<<(SEQ*32 + 255)/256, 256>>>();
    split_kernel<<<(1048576 + 255)/256, 256>>>(x, xh, xl, 1048576);
    concat_bias_kernel<<<(NLAYER*3072 + 255)/256, 256>>>(bq, bk, bv, bqkv, HID, HID, HID);
    interleave_bias_kernel<<<(NLAYER*AHID + 255)/256, 256>>>(b1, b3, b13i);
    {
        dim3 b(32, 8);
        transpose_split_kernel<<<dim3(32, 4, 1),  b>>>(in_w,  winh, winl, DIM,  HID, HID, DIM,  1, 0, 0, 0);
        transpose_split_kernel<<<dim3(32, 32, 6), b>>>(wq, wqkvh,            wqkvl,            HID, HID, HID, HID, 1, 0, HH, QKV);
        transpose_split_kernel<<<dim3(32, 32, 6), b>>>(wk, wqkvh + 1024*HID, wqkvl + 1024*HID, HID, HID, HID, HID, 1, 0, HH, QKV);
        transpose_split_kernel<<<dim3(32, 32, 6), b>>>(wv, wqkvh + 2048*HID, wqkvl + 2048*HID, HID, HID, HID, HID, 1, 0, HH, QKV);
        transpose_split_kernel<<<dim3(32, 32, 6), b>>>(wo, woh, wol, HID, HID, HID, HID, 1, 0, HH, HH);
        // interleaved w1/w3: dst row = 2c (w1), 2c+1 (w3)
        transpose_split_kernel<<<dim3(86, 32, 6), b>>>(w1, w13h, w13l, HID, AHID, AHID, HID, 2, 0, HA, F13);
        transpose_split_kernel<<<dim3(86, 32, 6), b>>>(w3, w13h, w13l, HID, AHID, AHID, HID, 2, 1, HA, F13);
        transpose_split_kernel<<<dim3(32, 86, 6), b>>>(w2, w2h, w2l, AHID, HID, HID, APAD, 1, 0, HA, (long long)HID*APAD);
        transpose_split_kernel<<<dim3(4, 32, 1),  b>>>(out_w, outwh, outwl, HID, DIM, DIM, HID, 1, 0, 0, 0);
    }

    // h = x @ in_w + in_b
    gemm(xh, xl, winh, winl, h, nullptr, nullptr, in_b,
         NTOK, HID, DIM, DIM, DIM, HID, 1.0f, 0, 0, 128);

    for (int l = 0; l < NLAYER; l++) {
        rmsnorm_kernel<<<NTOK, 256>>>(h, norm1_w + (long long)l*HID, gh, gl);

        // fused qkv: [NTOK][3072]
        gemm(gh, gl, wqkvh + l*QKV, wqkvl + l*QKV, qkvf, nullptr, nullptr, bqkv + (long long)l*3072,
             NTOK, 3072, HID, HID, HID, 3072, 1.0f, 0, 0, 128);

        rope_apply_kernel<<<(NTOK*NHEAD*32 + 255)/256, 256>>>(qkvf);
        transpose_split_kernel<<<dim3(32, 256, 1), dim3(32,8)>>>(qkvf + 2048, vth, vtl,
                                                                 NTOK, HID, 3072, NTOK, 1, 0, 0, 0);

        // scores = 0.125 * Q K^T  (z = b*NHEAD + head)
        gemm(qh, ql, kh, kl, sc, nullptr, nullptr, nullptr,
             SEQ, SEQ, HEADDIM, HID, HID, SEQ, 0.125f, 0, 0, 128,
             BATCH*NHEAD, NHEAD,
             (long long)SEQ*HID, HEADDIM,
             (long long)SEQ*HID, HEADDIM,
             (long long)NHEAD*SEQ*SEQ, (long long)SEQ*SEQ);

        softmax_kernel<<<BATCH*NHEAD*SEQ/8, 256>>>(sc, ph, pl);

        // o = P @ V  (bf16 hi/lo planes out)
        gemm(ph, pl, vth, vtl, nullptr, oh, ol, nullptr,
             SEQ, HEADDIM, SEQ, SEQ, NTOK, HID, 1.0f, 0, 1, 64,
             BATCH*NHEAD, NHEAD,
             (long long)NHEAD*SEQ*SEQ, (long long)SEQ*SEQ,
             (long long)SEQ, (long long)HEADDIM*NTOK,
             (long long)SEQ*HID, (long long)HEADDIM);

        // h += (o @ wo + bo) * RS
        gemm(oh, ol, woh + l*HH, wol + l*HH, h, nullptr, nullptr, bo + (long long)l*HID,
             NTOK, HID, HID, HID, HID, HID, RSCALE, 1, 0, 128);

        rmsnorm_kernel<<<NTOK, 256>>>(h, norm2_w + (long long)l*HID, gh, gl);

        // fused ff13 + SwiGLU epilogue -> ffg bf16 planes [NTOK][APAD]
        gemm(gh, gl, w13h + l*F13, w13l + l*F13, nullptr, ffh, ffl, b13i + (long long)l*5460,
             NTOK, 5460, HID, HID, HID, APAD, 1.0f, 0, 2, 128);

        // h += (ffg @ w2 + b2) * RS
        gemm(ffh, ffl, w2h + (long long)l*HID*APAD, w2l + (long long)l*HID*APAD, h,
             nullptr, nullptr, b2 + (long long)l*HID,
             NTOK, HID, AHID, APAD, APAD, HID, RSCALE, 1, 0, 128);
    }

    rmsnorm_kernel<<<NTOK, 256>>>(h, onorm_w, gh, gl);
    gemm(gh, gl, outwh, outwl, out, nullptr, nullptr, out_b,
         NTOK, DIM, HID, HID, HID, DIM, 1.0f, 0, 0, 128);
}

// round 13
// speedup vs baseline: 1.1875x; 1.0575x over previous
#include <cuda_runtime.h>
#include <cuda_bf16.h>
#include <cstdint>

#define BATCH   16
#define SEQ     512
#define DIM     128
#define HID     1024
#define NLAYER  6
#define NHEAD   16
#define HEADDIM 64
#define AHID    2730
#define APAD    2736
#define NTOK    8192
#define RSCALE  0.4082482904638630f
#define RMSEPS  1e-6f

#define SPITCH  40                // GEMM smem pitch (80B, conflict-free)

// ---------------------------------------------------------------------------
// Device scratch (allocation-free)
// ---------------------------------------------------------------------------
__device__ __nv_bfloat16 g_winh[131072],       g_winl[131072];
__device__ __nv_bfloat16 g_wqkvh[6*3145728],   g_wqkvl[6*3145728];   // [3072][1024]
__device__ __nv_bfloat16 g_woh [6*1048576],    g_wol [6*1048576];
__device__ __nv_bfloat16 g_w13h[6*5591040],    g_w13l[6*5591040];    // [5460][1024] interleaved w1/w3
__device__ __nv_bfloat16 g_w2h [6*1024*APAD],  g_w2l [6*1024*APAD];  // [1024][APAD]
__device__ __nv_bfloat16 g_outwh[131072],      g_outwl[131072];
__device__ __nv_bfloat16 g_xh [1048576],       g_xl [1048576];
__device__ __nv_bfloat16 g_gh [8388608],       g_gl [8388608];
__device__ __nv_bfloat16 g_qh [8388608],       g_ql [8388608];
__device__ __nv_bfloat16 g_kh [8388608],       g_kl [8388608];
__device__ __nv_bfloat16 g_vth[8388608],       g_vtl[8388608];       // [HID][NTOK]
__device__ __nv_bfloat16 g_oh [8388608],       g_ol [8388608];
__device__ __nv_bfloat16 g_ffh[(size_t)NTOK*APAD], g_ffl[(size_t)NTOK*APAD];
__device__ float g_h   [8388608];
__device__ float g_qkvf[(size_t)NTOK*3072];
__device__ float g_bqkv[6*3072];
__device__ float g_b13i[6*5460];
__device__ float g_cos [SEQ*32], g_sin[SEQ*32];

// ---------------------------------------------------------------------------
// PTX helpers
// ---------------------------------------------------------------------------
__device__ __forceinline__ void cp_async16(uint32_t dst, const void* src, int srcbytes) {
    asm volatile("cp.async.cg.shared.global [%0], [%1], 16, %2;\n"
                 :: "r"(dst), "l"(src), "r"(srcbytes));
}
#define CP_COMMIT() asm volatile("cp.async.commit_group;\n" ::)
#define CP_WAIT(n)  asm volatile("cp.async.wait_group %0;\n" :: "n"(n))

#define LDSM4(R0,R1,R2,R3,addr)                                               \
  asm volatile("ldmatrix.sync.aligned.m8n8.x4.shared.b16 {%0,%1,%2,%3}, [%4];"\
               : "=r"(R0),"=r"(R1),"=r"(R2),"=r"(R3) : "r"(addr))

#define MMA16816(d, A0,A1,A2,A3, B0,B1)                                       \
  asm volatile("mma.sync.aligned.m16n8k16.row.col.f32.bf16.bf16.f32 "         \
               "{%0,%1,%2,%3}, {%4,%5,%6,%7}, {%8,%9}, {%0,%1,%2,%3};"        \
               : "+f"(d[0]), "+f"(d[1]), "+f"(d[2]), "+f"(d[3])               \
               : "r"(A0), "r"(A1), "r"(A2), "r"(A3), "r"(B0), "r"(B1))

__device__ __forceinline__ void split_pack(float x, float y, uint32_t& hi, uint32_t& lo) {
    __nv_bfloat16 hx = __float2bfloat16(x);
    __nv_bfloat16 hy = __float2bfloat16(y);
    __nv_bfloat16 lx = __float2bfloat16(x - __bfloat162float(hx));
    __nv_bfloat16 ly = __float2bfloat16(y - __bfloat162float(hy));
    hi = ((uint32_t)__bfloat16_as_ushort(hy) << 16) | __bfloat16_as_ushort(hx);
    lo = ((uint32_t)__bfloat16_as_ushort(ly) << 16) | __bfloat16_as_ushort(lx);
}

// ---------------------------------------------------------------------------
// Fused flash attention. CTA = (qtile, b*NH+h). 8 warps x 16 q-rows.
// Key tiles of 64, double-buffered. 3-term hi/lo split throughout.
// Q/K from [NTOK][HID] planes; V^T from [HID][NTOK] planes; O -> [NTOK][HID] planes.
// smem (bf16 elems): Qh 128x72 @0, Ql @9216; stage s @18432+s*18432:
//   Kh 64x72 +0, Kl +4608, Vh 64x72 +9216, Vl +13824.  Total 55296 el = 110592 B.
// ---------------------------------------------------------------------------
#define FA_SMEM 110592

__global__ void __launch_bounds__(256, 2)
flash_attn_kernel(const __nv_bfloat16* __restrict__ qh_, const __nv_bfloat16* __restrict__ ql_,
                  const __nv_bfloat16* __restrict__ kh_, const __nv_bfloat16* __restrict__ kl_,
                  const __nv_bfloat16* __restrict__ vh_, const __nv_bfloat16* __restrict__ vl_,
                  __nv_bfloat16* __restrict__ oh_, __nv_bfloat16* __restrict__ ol_)
{
    extern __shared__ __nv_bfloat16 sm[];
    uint32_t sb = (uint32_t)__cvta_generic_to_shared(sm);

    const int tid = threadIdx.x, lane = tid & 31, warp = tid >> 5;
    const int g = lane >> 2, t4 = lane & 3;
    const int rr = lane & 15;
    const int chalf = (lane >> 4) << 3;

    const int bh = blockIdx.y;
    const int b = bh >> 4, h = bh & 15;
    const int tok0 = b * SEQ + blockIdx.x * 128;
    const int h64 = h * HEADDIM;

    // ---- load Q tile (128 x 64, hi/lo) ----
    #pragma unroll
    for (int i = 0; i < 4; i++) {
        int idx = tid + i * 256;
        int r = idx >> 3, ch = idx & 7;
        long long src = (long long)(tok0 + r) * HID + h64 + ch * 8;
        uint32_t d = sb + (uint32_t)(r * 72 + ch * 8) * 2;
        cp_async16(d,           qh_ + src, 16);
        cp_async16(d + 9216*2,  ql_ + src, 16);
    }

    auto loadKV = [&](int stage, int t) {
        uint32_t st = sb + (uint32_t)(18432 + stage * 18432) * 2;
        #pragma unroll
        for (int i = 0; i < 2; i++) {
            int idx = tid + i * 256;
            int r = idx >> 3, ch = idx & 7;
            long long ksrc = (long long)(b * SEQ + t * 64 + r) * HID + h64 + ch * 8;
            uint32_t kd = st + (uint32_t)(r * 72 + ch * 8) * 2;
            cp_async16(kd,            kh_ + ksrc, 16);
            cp_async16(kd + 4608*2,   kl_ + ksrc, 16);
            long long vsrc = (long long)(h64 + r) * NTOK + b * SEQ + t * 64 + ch * 8;
            uint32_t vd = st + (uint32_t)(9216 + r * 72 + ch * 8) * 2;
            cp_async16(vd,            vh_ + vsrc, 16);
            cp_async16(vd + 4608*2,   vl_ + vsrc, 16);
        }
    };

    loadKV(0, 0);
    CP_COMMIT();

    float oacc[8][4];
    #pragma unroll
    for (int nt = 0; nt < 8; nt++)
        #pragma unroll
        for (int e = 0; e < 4; e++) oacc[nt][e] = 0.f;
    float m0 = -1e30f, m1 = -1e30f, l0 = 0.f, l1 = 0.f;

    for (int t = 0; t < 8; t++) {
        CP_WAIT(0);
        __syncthreads();
        if (t + 1 < 8) { loadKV((t + 1) & 1, t + 1); CP_COMMIT(); }

        const uint32_t KHb = 18432u + (uint32_t)(t & 1) * 18432u;
        const uint32_t VHb = KHb + 9216u;

        // ---- S = Q K^T (3 split terms), warp rows [warp*16, +16), keys 64 ----
        float sacc[8][4];
        #pragma unroll
        for (int nt = 0; nt < 8; nt++)
            #pragma unroll
            for (int e = 0; e < 4; e++) sacc[nt][e] = 0.f;

        #pragma unroll
        for (int ks = 0; ks < 4; ks++) {
            const int c0 = ks * 16 + chalf;
            uint32_t ah[4], al[4];
            uint32_t ad = sb + (uint32_t)((warp * 16 + rr) * 72 + c0) * 2;
            LDSM4(ah[0], ah[1], ah[2], ah[3], ad);
            LDSM4(al[0], al[1], al[2], al[3], ad + 9216*2);
            uint32_t bh4[8][2], bl4[8][2];
            #pragma unroll
            for (int p = 0; p < 4; p++) {
                uint32_t bd = sb + (uint32_t)(KHb + (p * 16 + rr) * 72 + c0) * 2;
                uint32_t r0, r1, r2, r3;
                LDSM4(r0, r1, r2, r3, bd);
                bh4[2*p][0] = r0; bh4[2*p+1][0] = r1; bh4[2*p][1] = r2; bh4[2*p+1][1] = r3;
                LDSM4(r0, r1, r2, r3, bd + 4608*2);
                bl4[2*p][0] = r0; bl4[2*p+1][0] = r1; bl4[2*p][1] = r2; bl4[2*p+1][1] = r3;
            }
            #pragma unroll
            for (int nt = 0; nt < 8; nt++)
                MMA16816(sacc[nt], ah[0],ah[1],ah[2],ah[3], bh4[nt][0], bh4[nt][1]);
            #pragma unroll
            for (int nt = 0; nt < 8; nt++)
                MMA16816(sacc[nt], ah[0],ah[1],ah[2],ah[3], bl4[nt][0], bl4[nt][1]);
            #pragma unroll
            for (int nt = 0; nt < 8; nt++)
                MMA16816(sacc[nt], al[0],al[1],al[2],al[3], bh4[nt][0], bh4[nt][1]);
        }

        // ---- online softmax ----
        float mx0 = -1e30f, mx1 = -1e30f;
        #pragma unroll
        for (int nt = 0; nt < 8; nt++) {
            sacc[nt][0] *= 0.125f; sacc[nt][1] *= 0.125f;
            sacc[nt][2] *= 0.125f; sacc[nt][3] *= 0.125f;
            mx0 = fmaxf(mx0, fmaxf(sacc[nt][0], sacc[nt][1]));
            mx1 = fmaxf(mx1, fmaxf(sacc[nt][2], sacc[nt][3]));
        }
        mx0 = fmaxf(mx0, __shfl_xor_sync(0xffffffffu, mx0, 1));
        mx0 = fmaxf(mx0, __shfl_xor_sync(0xffffffffu, mx0, 2));
        mx1 = fmaxf(mx1, __shfl_xor_sync(0xffffffffu, mx1, 1));
        mx1 = fmaxf(mx1, __shfl_xor_sync(0xffffffffu, mx1, 2));
        float mn0 = fmaxf(m0, mx0), mn1 = fmaxf(m1, mx1);
        float sc0 = __expf(m0 - mn0), sc1 = __expf(m1 - mn1);
        float rs0 = 0.f, rs1 = 0.f;
        #pragma unroll
        for (int nt = 0; nt < 8; nt++) {
            sacc[nt][0] = __expf(sacc[nt][0] - mn0); rs0 += sacc[nt][0];
            sacc[nt][1] = __expf(sacc[nt][1] - mn0); rs0 += sacc[nt][1];
            sacc[nt][2] = __expf(sacc[nt][2] - mn1); rs1 += sacc[nt][2];
            sacc[nt][3] = __expf(sacc[nt][3] - mn1); rs1 += sacc[nt][3];
        }
        rs0 += __shfl_xor_sync(0xffffffffu, rs0, 1);
        rs0 += __shfl_xor_sync(0xffffffffu, rs0, 2);
        rs1 += __shfl_xor_sync(0xffffffffu, rs1, 1);
        rs1 += __shfl_xor_sync(0xffffffffu, rs1, 2);
        l0 = l0 * sc0 + rs0;  l1 = l1 * sc1 + rs1;
        m0 = mn0;  m1 = mn1;
        #pragma unroll
        for (int nt = 0; nt < 8; nt++) {
            oacc[nt][0] *= sc0; oacc[nt][1] *= sc0;
            oacc[nt][2] *= sc1; oacc[nt][3] *= sc1;
        }

        // ---- O += P V (P split in-register) ----
        #pragma unroll
        for (int j = 0; j < 4; j++) {
            uint32_t aPh[4], aPl[4];
            split_pack(sacc[2*j  ][0], sacc[2*j  ][1], aPh[0], aPl[0]);
            split_pack(sacc[2*j  ][2], sacc[2*j  ][3], aPh[1], aPl[1]);
            split_pack(sacc[2*j+1][0], sacc[2*j+1][1], aPh[2], aPl[2]);
            split_pack(sacc[2*j+1][2], sacc[2*j+1][3], aPh[3], aPl[3]);
            const int c0v = j * 16 + chalf;
            uint32_t bvh[8][2], bvl[8][2];
            #pragma unroll
            for (int p = 0; p < 4; p++) {
                uint32_t bd = sb + (uint32_t)(VHb + (p * 16 + rr) * 72 + c0v) * 2;
                uint32_t r0, r1, r2, r3;
                LDSM4(r0, r1, r2, r3, bd);
                bvh[2*p][0] = r0; bvh[2*p+1][0] = r1; bvh[2*p][1] = r2; bvh[2*p+1][1] = r3;
                LDSM4(r0, r1, r2, r3, bd + 4608*2);
                bvl[2*p][0] = r0; bvl[2*p+1][0] = r1; bvl[2*p][1] = r2; bvl[2*p+1][1] = r3;
            }
            #pragma unroll
            for (int nt = 0; nt < 8; nt++)
                MMA16816(oacc[nt], aPh[0],aPh[1],aPh[2],aPh[3], bvh[nt][0], bvh[nt][1]);
            #pragma unroll
            for (int nt = 0; nt < 8; nt++)
                MMA16816(oacc[nt], aPl[0],aPl[1],aPl[2],aPl[3], bvh[nt][0], bvh[nt][1]);
            #pragma unroll
            for (int nt = 0; nt < 8; nt++)
                MMA16816(oacc[nt], aPh[0],aPh[1],aPh[2],aPh[3], bvl[nt][0], bvl[nt][1]);
        }
    }

    // ---- epilogue: O /= l, write hi/lo planes ----
    float inv0 = 1.f / l0, inv1 = 1.f / l1;
    const int row0 = tok0 + warp * 16 + g;
    #pragma unroll
    for (int nt = 0; nt < 8; nt++) {
        int c = h64 + nt * 8 + 2 * t4;
        uint32_t hi, lo;
        split_pack(oacc[nt][0] * inv0, oacc[nt][1] * inv0, hi, lo);
        long long off = (long long)row0 * HID + c;
        *(uint32_t*)(oh_ + off) = hi;
        *(uint32_t*)(ol_ + off) = lo;
        split_pack(oacc[nt][2] * inv1, oacc[nt][3] * inv1, hi, lo);
        off = (long long)(row0 + 8) * HID + c;
        *(uint32_t*)(oh_ + off) = hi;
        *(uint32_t*)(ol_ + off) = lo;
    }
}

// ---------------------------------------------------------------------------
// Pipelined bf16 split GEMM (2 CTAs/SM, double-buffered) — unchanged from R8
// ---------------------------------------------------------------------------
template<int NT, int WR, int WC>
__global__ void __launch_bounds__(256, 2)
gemm_mma_kernel(const __nv_bfloat16* __restrict__ Ah, const __nv_bfloat16* __restrict__ Al,
                const __nv_bfloat16* __restrict__ Bh, const __nv_bfloat16* __restrict__ Bl,
                float* __restrict__ C, __nv_bfloat16* __restrict__ Ch, __nv_bfloat16* __restrict__ Cl,
                const float* __restrict__ bias,
                int M, int N, int K, int lda, int ldb, int ldc,
                float alpha, int accum, int outmode, int bdiv,
                long long sA1, long long sA2, long long sB1, long long sB2,
                long long sC1, long long sC2)
{
    constexpr int WTM = 128 / WR;
    constexpr int WTN = NT / WC;
    constexpr int MT  = WTM / 16;
    constexpr int NTT = WTN / 8;
    constexpr int NH  = NTT / 4;
    constexpr int APLANE = 128 * SPITCH;
    constexpr int BPLANE = NT * SPITCH;
    constexpr int STAGE_E = 2*APLANE + 2*BPLANE;

    extern __shared__ __nv_bfloat16 smem[];
    uint32_t sbase = (uint32_t)__cvta_generic_to_shared(smem);

    const int tid = threadIdx.x, lane = tid & 31, warp = tid >> 5;
    const int wm = warp / WC, wn = warp % WC;

    const int z = blockIdx.z, zq = z / bdiv, zr = z - zq * bdiv;
    const __nv_bfloat16* Abh = Ah + zq*sA1 + (long long)zr*sA2;
    const __nv_bfloat16* Abl = Al + zq*sA1 + (long long)zr*sA2;
    const __nv_bfloat16* Bbh = Bh + zq*sB1 + (long long)zr*sB2;
    const __nv_bfloat16* Bbl = Bl + zq*sB1 + (long long)zr*sB2;
    const long long coff = zq*sC1 + (long long)zr*sC2;

    const int m0 = blockIdx.y * 128, n0 = blockIdx.x * NT;
    const int T = (K + 31) >> 5;

    auto load_stage = [&](int stg, int k0) {
        uint32_t st = sbase + (uint32_t)stg * (STAGE_E * 2);
        #pragma unroll
        for (int i = 0; i < 2; i++) {
            int idx = tid + i*256;
            int r = idx >> 2, ch = idx & 3;
            int k = k0 + ch*8;
            int s = (K - k) * 2; s = s < 0 ? 0 : (s > 16 ? 16 : s);
            long long aoff = (long long)(m0 + r) * lda + (s ? k : 0);
            uint32_t d = st + (uint32_t)(r*SPITCH + ch*8)*2;
            cp_async16(d,            Abh + aoff, s);
            cp_async16(d + APLANE*2, Abl + aoff, s);
        }
        #pragma unroll
        for (int i = 0; i < NT/64; i++) {
            int idx = tid + i*256;
            int r = idx >> 2, ch = idx & 3;
            int n = n0 + r;
            int k = k0 + ch*8;
            int s = (K - k) * 2; s = s < 0 ? 0 : (s > 16 ? 16 : s);
            if (n >= N) s = 0;
            long long boff = (long long)(n < N ? n : 0) * ldb + (s ? k : 0);
            uint32_t d = st + (uint32_t)(2*APLANE + r*SPITCH + ch*8)*2;
            cp_async16(d,            Bbh + boff, s);
            cp_async16(d + BPLANE*2, Bbl + boff, s);
        }
    };

    load_stage(0, 0);
    CP_COMMIT();

    float acc[MT][NTT][4];
    #pragma unroll
    for (int i = 0; i < MT; i++)
        #pragma unroll
        for (int j = 0; j < NTT; j++)
            #pragma unroll
            for (int e = 0; e < 4; e++) acc[i][j][e] = 0.f;

    for (int kt = 0; kt < T; kt++) {
        CP_WAIT(0);
        __syncthreads();
        if (kt + 1 < T) { load_stage((kt + 1) & 1, (kt + 1) * 32); CP_COMMIT(); }

        uint32_t st = sbase + (uint32_t)((kt & 1) * (STAGE_E * 2));
        #pragma unroll
        for (int ks = 0; ks < 2; ks++) {
            const int c0 = ks*16 + ((lane >> 4) << 3);
            const int rr = lane & 15;
            uint32_t ah[MT][4], al[MT][4];
            #pragma unroll
            for (int mt = 0; mt < MT; mt++) {
                uint32_t ad = st + (uint32_t)(((wm*WTM + mt*16 + rr)*SPITCH + c0)*2);
                LDSM4(ah[mt][0], ah[mt][1], ah[mt][2], ah[mt][3], ad);
                LDSM4(al[mt][0], al[mt][1], al[mt][2], al[mt][3], ad + APLANE*2);
            }
            #pragma unroll
            for (int half = 0; half < NH; half++) {
                uint32_t bh4[4][2], bl4[4][2];
                #pragma unroll
                for (int p = 0; p < 2; p++) {
                    uint32_t bd = st + (uint32_t)((2*APLANE +
                                  (wn*WTN + half*32 + p*16 + rr)*SPITCH + c0)*2);
                    uint32_t r0, r1, r2, r3;
                    LDSM4(r0, r1, r2, r3, bd);
                    bh4[2*p][0] = r0; bh4[2*p+1][0] = r1; bh4[2*p][1] = r2; bh4[2*p+1][1] = r3;
                    LDSM4(r0, r1, r2, r3, bd + BPLANE*2);
                    bl4[2*p][0] = r0; bl4[2*p+1][0] = r1; bl4[2*p][1] = r2; bl4[2*p+1][1] = r3;
                }
                #pragma unroll
                for (int mt = 0; mt < MT; mt++)
                    #pragma unroll
                    for (int j = 0; j < 4; j++)
                        MMA16816(acc[mt][half*4+j], ah[mt][0],ah[mt][1],ah[mt][2],ah[mt][3], bh4[j][0],bh4[j][1]);
                #pragma unroll
                for (int mt = 0; mt < MT; mt++)
                    #pragma unroll
                    for (int j = 0; j < 4; j++)
                        MMA16816(acc[mt][half*4+j], ah[mt][0],ah[mt][1],ah[mt][2],ah[mt][3], bl4[j][0],bl4[j][1]);
                #pragma unroll
                for (int mt = 0; mt < MT; mt++)
                    #pragma unroll
                    for (int j = 0; j < 4; j++)
                        MMA16816(acc[mt][half*4+j], al[mt][0],al[mt][1],al[mt][2],al[mt][3], bh4[j][0],bh4[j][1]);
            }
        }
    }

    const int g = lane >> 2, t4 = lane & 3;
    #pragma unroll
    for (int mt = 0; mt < MT; mt++)
        #pragma unroll
        for (int nt = 0; nt < NTT; nt++) {
            int r = m0 + wm*WTM + mt*16 + g;
            int c = n0 + wn*WTN + nt*8 + 2*t4;
            if (c < N) {
                float bv0 = 0.f, bv1 = 0.f;
                if (bias) { bv0 = bias[c]; bv1 = bias[c+1]; }
                #pragma unroll
                for (int hh = 0; hh < 2; hh++) {
                    int rr = r + hh*8;
                    float v0 = acc[mt][nt][hh*2+0] + bv0;
                    float v1 = acc[mt][nt][hh*2+1] + bv1;
                    if (outmode == 0) {
                        v0 *= alpha; v1 *= alpha;
                        long long off = coff + (long long)rr * ldc + c;
                        float2 o;
                        if (accum) { float2 p = *(const float2*)(C + off); o.x = p.x + v0; o.y = p.y + v1; }
                        else       { o.x = v0; o.y = v1; }
                        *(float2*)(C + off) = o;
                    } else if (outmode == 1) {
                        v0 *= alpha; v1 *= alpha;
                        long long off = coff + (long long)rr * ldc + c;
                        uint32_t ph, pl;
                        split_pack(v0, v1, ph, pl);
                        *(uint32_t*)(Ch + off) = ph;
                        *(uint32_t*)(Cl + off) = pl;
                    } else {
                        float v = v0 / (1.0f + __expf(-v0)) * v1;
                        long long off = coff + (long long)rr * ldc + (c >> 1);
                        __nv_bfloat16 hi = __float2bfloat16(v);
                        Ch[off] = hi;
                        Cl[off] = __float2bfloat16(v - __bfloat162float(hi));
                    }
                }
            }
        }
}

// ---------------------------------------------------------------------------
// Producers / converters
// ---------------------------------------------------------------------------
__global__ void split_kernel(const float* __restrict__ src,
                             __nv_bfloat16* __restrict__ dh,
                             __nv_bfloat16* __restrict__ dl, long long n)
{
    long long i = (long long)blockIdx.x * blockDim.x + threadIdx.x;
    if (i >= n) return;
    float v = src[i];
    __nv_bfloat16 hi = __float2bfloat16(v);
    dh[i] = hi;
    dl[i] = __float2bfloat16(v - __bfloat162float(hi));
}

__global__ void transpose_split_kernel(const float* __restrict__ src,
                                       __nv_bfloat16* __restrict__ dh,
                                       __nv_bfloat16* __restrict__ dl,
                                       int R, int C, int srcPitch, int dstPitch,
                                       int rowMul, int rowAdd,
                                       long long srcZ, long long dstZ)
{
    __shared__ float t[32][33];
    long long so = (long long)blockIdx.z * srcZ;
    long long dofs = (long long)blockIdx.z * dstZ;
    int c0 = blockIdx.x*32, r0 = blockIdx.y*32;
    #pragma unroll
    for (int i = threadIdx.y; i < 32; i += 8) {
        int r = r0 + i, c = c0 + threadIdx.x;
        t[i][threadIdx.x] = (r < R && c < C) ? src[so + (long long)r*srcPitch + c] : 0.f;
    }
    __syncthreads();
    #pragma unroll
    for (int i = threadIdx.y; i < 32; i += 8) {
        int c = c0 + i, r = r0 + threadIdx.x;
        if (c < C && r < R) {
            float v = t[threadIdx.x][i];
            __nv_bfloat16 hi = __float2bfloat16(v);
            long long o = dofs + (long long)(c*rowMul + rowAdd)*dstPitch + r;
            dh[o] = hi;
            dl[o] = __float2bfloat16(v - __bfloat162float(hi));
        }
    }
}

__global__ void rmsnorm_kernel(const float* __restrict__ x, const float* __restrict__ w,
                               __nv_bfloat16* __restrict__ oh, __nv_bfloat16* __restrict__ ol)
{
    long long row = blockIdx.x;
    const float* xr = x + row * HID;
    float s = 0.f;
    #pragma unroll
    for (int c = threadIdx.x; c < HID; c += 256) { float v = xr[c]; s += v * v; }
    #pragma unroll
    for (int o = 16; o; o >>= 1) s += __shfl_xor_sync(0xffffffffu, s, o);
    __shared__ float red[8];
    int warp = threadIdx.x >> 5, lane = threadIdx.x & 31;
    if (lane == 0) red[warp] = s;
    __syncthreads();
    float tot = red[0]+red[1]+red[2]+red[3]+red[4]+red[5]+red[6]+red[7];
    float inv = rsqrtf(tot * (1.0f / HID) + RMSEPS);
    #pragma unroll
    for (int c = threadIdx.x; c < HID; c += 256) {
        float v = xr[c] * inv * w[c];
        __nv_bfloat16 hi = __float2bfloat16(v);
        oh[row*HID + c] = hi;
        ol[row*HID + c] = __float2bfloat16(v - __bfloat162float(hi));
    }
}

__global__ void rope_cache_kernel()
{
    int i = blockIdx.x * blockDim.x + threadIdx.x;
    if (i >= SEQ * 32) return;
    int s = i >> 5, j = i & 31;
    float invf = expf(-(float)j * (1.0f / 32.0f) * logf(10000.0f));
    float a = (float)s * invf;
    g_cos[i] = cosf(a);
    g_sin[i] = sinf(a);
}

__global__ void rope_apply_kernel(const float* __restrict__ qkv)
{
    int i = blockIdx.x * blockDim.x + threadIdx.x;
    if (i >= NTOK * NHEAD * 32) return;
    int m = i >> 9, rem = i & 511;
    int h = rem >> 5, j = rem & 31;
    int s = m & (SEQ - 1);
    float c  = g_cos[s*32 + j];
    float sn = g_sin[s*32 + j];
    long long src = (long long)m * 3072 + h * HEADDIM + j;
    long long dst = (long long)m * HID  + h * HEADDIM + j;
    {
        float a = qkv[src], b = qkv[src + 32];
        float v0 = a * c - b * sn, v1 = b * c + a * sn;
        __nv_bfloat16 h0 = __float2bfloat16(v0), h1 = __float2bfloat16(v1);
        g_qh[dst]      = h0; g_ql[dst]      = __float2bfloat16(v0 - __bfloat162float(h0));
        g_qh[dst + 32] = h1; g_ql[dst + 32] = __float2bfloat16(v1 - __bfloat162float(h1));
    }
    {
        float a = qkv[src + HID], b = qkv[src + HID + 32];
        float v0 = a * c - b * sn, v1 = b * c + a * sn;
        __nv_bfloat16 h0 = __float2bfloat16(v0), h1 = __float2bfloat16(v1);
        g_kh[dst]      = h0; g_kl[dst]      = __float2bfloat16(v0 - __bfloat162float(h0));
        g_kh[dst + 32] = h1; g_kl[dst + 32] = __float2bfloat16(v1 - __bfloat162float(h1));
    }
}

__global__ void interleave_bias_kernel(const float* __restrict__ b1, const float* __restrict__ b3,
                                       float* __restrict__ dst)
{
    int i = blockIdx.x * blockDim.x + threadIdx.x;
    if (i >= NLAYER * AHID) return;
    int l = i / AHID, j = i - l * AHID;
    dst[(long long)l*5460 + 2*j]     = b1[(long long)l*AHID + j];
    dst[(long long)l*5460 + 2*j + 1] = b3[(long long)l*AHID + j];
}

__global__ void concat_bias_kernel(const float* __restrict__ b1, const float* __restrict__ b2,
                                   const float* __restrict__ b3, float* __restrict__ dst,
                                   int n1, int n2, int n3)
{
    int tot = n1 + n2 + n3;
    int i = blockIdx.x * blockDim.x + threadIdx.x;
    if (i >= NLAYER * tot) return;
    int l = i / tot, r = i - l * tot;
    float v;
    if (r < n1)           v = b1[l*n1 + r];
    else if (r < n1 + n2) v = b2[l*n2 + (r - n1)];
    else                  v = b3[l*n3 + (r - n1 - n2)];
    dst[i] = v;
}

// ---------------------------------------------------------------------------
// Host plumbing
// ---------------------------------------------------------------------------
static inline size_t stage_bytes(int NT) { return (size_t)(2*128*SPITCH + 2*NT*SPITCH) * 2; }

static void gemm(const __nv_bfloat16* Ahp, const __nv_bfloat16* Alp,
                 const __nv_bfloat16* Bhp, const __nv_bfloat16* Blp,
                 float* C, __nv_bfloat16* Ch, __nv_bfloat16* Cl,
                 const float* bias, int M, int N, int K, int lda, int ldb, int ldc,
                 float alpha, int accum, int outmode)
{
    dim3 grid((N + 127) / 128, M / 128, 1);
    size_t sm = 2 * stage_bytes(128);
    gemm_mma_kernel<128,4,2><<<grid, 256, sm>>>(Ahp, Alp, Bhp, Blp, C, Ch, Cl, bias,
        M, N, K, lda, ldb, ldc, alpha, accum, outmode, 1, 0, 0, 0, 0, 0, 0);
}

#define SYM(p, s) cudaGetSymbolAddress((void**)&p, s)

extern "C" void kernel_launch(void* const* d_in, const int* in_sizes, int n_in,
                              void* d_out, int out_size)
{
    const float* x       = (const float*)d_in[0];
    const float* in_w    = (const float*)d_in[1];
    const float* in_b    = (const float*)d_in[2];
    const float* norm1_w = (const float*)d_in[3];
    const float* norm2_w = (const float*)d_in[4];
    const float* wq      = (const float*)d_in[5];
    const float* bq      = (const float*)d_in[6];
    const float* wk      = (const float*)d_in[7];
    const float* bk      = (const float*)d_in[8];
    const float* wv      = (const float*)d_in[9];
    const float* bv      = (const float*)d_in[10];
    const float* wo      = (const float*)d_in[11];
    const float* bo      = (const float*)d_in[12];
    const float* w1      = (const float*)d_in[13];
    const float* b1      = (const float*)d_in[14];
    const float* w3      = (const float*)d_in[15];
    const float* b3      = (const float*)d_in[16];
    const float* w2      = (const float*)d_in[17];
    const float* b2      = (const float*)d_in[18];
    const float* onorm_w = (const float*)d_in[19];
    const float* out_w   = (const float*)d_in[20];
    const float* out_b   = (const float*)d_in[21];
    float* out = (float*)d_out;

    cudaFuncSetAttribute(gemm_mma_kernel<128,4,2>,
        cudaFuncAttributeMaxDynamicSharedMemorySize, (int)(2 * stage_bytes(128)));
    cudaFuncSetAttribute(flash_attn_kernel,
        cudaFuncAttributeMaxDynamicSharedMemorySize, FA_SMEM);

    __nv_bfloat16 *winh,*winl,*wqkvh,*wqkvl,*woh,*wol,*w13h,*w13l,*w2h,*w2l,*outwh,*outwl;
    __nv_bfloat16 *xh,*xl,*gh,*gl,*qh,*ql,*kh,*kl,*vth,*vtl,*oh,*ol,*ffh,*ffl;
    float *h,*qkvf,*bqkv,*b13i;
    SYM(winh,g_winh); SYM(winl,g_winl);
    SYM(wqkvh,g_wqkvh); SYM(wqkvl,g_wqkvl);
    SYM(woh,g_woh); SYM(wol,g_wol);
    SYM(w13h,g_w13h); SYM(w13l,g_w13l);
    SYM(w2h,g_w2h); SYM(w2l,g_w2l);
    SYM(outwh,g_outwh); SYM(outwl,g_outwl);
    SYM(xh,g_xh); SYM(xl,g_xl); SYM(gh,g_gh); SYM(gl,g_gl);
    SYM(qh,g_qh); SYM(ql,g_ql); SYM(kh,g_kh); SYM(kl,g_kl);
    SYM(vth,g_vth); SYM(vtl,g_vtl); SYM(oh,g_oh); SYM(ol,g_ol);
    SYM(ffh,g_ffh); SYM(ffl,g_ffl);
    SYM(h,g_h); SYM(qkvf,g_qkvf);
    SYM(bqkv,g_bqkv); SYM(b13i,g_b13i);

    const long long HH  = (long long)HID*HID;
    const long long HA  = (long long)HID*AHID;
    const long long QKV = (long long)3072*HID;
    const long long F13 = (long long)5460*HID;

    rope_cache_kernel<<<(SEQ*32 + 255)/256, 256>>>();
    split_kernel<<<(1048576 + 255)/256, 256>>>(x, xh, xl, 1048576);
    concat_bias_kernel<<<(NLAYER*3072 + 255)/256, 256>>>(bq, bk, bv, bqkv, HID, HID, HID);
    interleave_bias_kernel<<<(NLAYER*AHID + 255)/256, 256>>>(b1, b3, b13i);
    {
        dim3 b(32, 8);
        transpose_split_kernel<<<dim3(32, 4, 1),  b>>>(in_w,  winh, winl, DIM,  HID, HID, DIM,  1, 0, 0, 0);
        transpose_split_kernel<<<dim3(32, 32, 6), b>>>(wq, wqkvh,            wqkvl,            HID, HID, HID, HID, 1, 0, HH, QKV);
        transpose_split_kernel<<<dim3(32, 32, 6), b>>>(wk, wqkvh + 1024*HID, wqkvl + 1024*HID, HID, HID, HID, HID, 1, 0, HH, QKV);
        transpose_split_kernel<<<dim3(32, 32, 6), b>>>(wv, wqkvh + 2048*HID, wqkvl + 2048*HID, HID, HID, HID, HID, 1, 0, HH, QKV);
        transpose_split_kernel<<<dim3(32, 32, 6), b>>>(wo, woh, wol, HID, HID, HID, HID, 1, 0, HH, HH);
        transpose_split_kernel<<<dim3(86, 32, 6), b>>>(w1, w13h, w13l, HID, AHID, AHID, HID, 2, 0, HA, F13);
        transpose_split_kernel<<<dim3(86, 32, 6), b>>>(w3, w13h, w13l, HID, AHID, AHID, HID, 2, 1, HA, F13);
        transpose_split_kernel<<<dim3(32, 86, 6), b>>>(w2, w2h, w2l, AHID, HID, HID, APAD, 1, 0, HA, (long long)HID*APAD);
        transpose_split_kernel<<<dim3(4, 32, 1),  b>>>(out_w, outwh, outwl, HID, DIM, DIM, HID, 1, 0, 0, 0);
    }

    // h = x @ in_w + in_b
    gemm(xh, xl, winh, winl, h, nullptr, nullptr, in_b,
         NTOK, HID, DIM, DIM, DIM, HID, 1.0f, 0, 0);

    for (int l = 0; l < NLAYER; l++) {
        rmsnorm_kernel<<<NTOK, 256>>>(h, norm1_w + (long long)l*HID, gh, gl);

        gemm(gh, gl, wqkvh + l*QKV, wqkvl + l*QKV, qkvf, nullptr, nullptr, bqkv + (long long)l*3072,
             NTOK, 3072, HID, HID, HID, 3072, 1.0f, 0, 0);

        rope_apply_kernel<<<(NTOK*NHEAD*32 + 255)/256, 256>>>(qkvf);
        transpose_split_kernel<<<dim3(32, 256, 1), dim3(32,8)>>>(qkvf + 2048, vth, vtl,
                                                                 NTOK, HID, 3072, NTOK, 1, 0, 0, 0);

        // fused flash attention -> o planes
        flash_attn_kernel<<<dim3(4, 256), 256, FA_SMEM>>>(qh, ql, kh, kl, vth, vtl, oh, ol);

        // h += (o @ wo + bo) * RS
        gemm(oh, ol, woh + l*HH, wol + l*HH, h, nullptr, nullptr, bo + (long long)l*HID,
             NTOK, HID, HID, HID, HID, HID, RSCALE, 1, 0);

        rmsnorm_kernel<<<NTOK, 256>>>(h, norm2_w + (long long)l*HID, gh, gl);

        // fused ff13 + SwiGLU epilogue -> ffg bf16 planes [NTOK][APAD]
        gemm(gh, gl, w13h + l*F13, w13l + l*F13, nullptr, ffh, ffl, b13i + (long long)l*5460,
             NTOK, 5460, HID, HID, HID, APAD, 1.0f, 0, 2);

        // h += (ffg @ w2 + b2) * RS
        gemm(ffh, ffl, w2h + (long long)l*HID*APAD, w2l + (long long)l*HID*APAD, h,
             nullptr, nullptr, b2 + (long long)l*HID,
             NTOK, HID, AHID, APAD, APAD, HID, RSCALE, 1, 0);
    }

    rmsnorm_kernel<<<NTOK, 256>>>(h, onorm_w, gh, gl);
    gemm(gh, gl, outwh, outwl, out, nullptr, nullptr, out_b,
         NTOK, DIM, HID, HID, HID, DIM, 1.0f, 0, 0);
}